// round 1
// baseline (speedup 1.0000x reference)
#include <cuda_runtime.h>
#include <math.h>

#define NB 4
#define LQ 2048
#define SK 4096
#define CH 256
#define NH 8
#define DH 32
#define HID 1024
#define NLROWS (NB*LQ)      // 8192
#define NSROWS (NB*SK)      // 16384

// ---------------- scratch (device globals; no runtime alloc) ----------------
__device__ float g_tgt2[NLROWS*CH];
__device__ float g_qk  [NLROWS*CH];
__device__ float g_q   [NLROWS*CH];
__device__ float g_k   [NLROWS*CH];
__device__ float g_v   [NLROWS*CH];
__device__ float g_lao [NLROWS*CH];
__device__ float g_t1  [NLROWS*CH];
__device__ float g_cq  [NLROWS*CH];
__device__ float g_co  [NLROWS*CH];
__device__ float g_t2  [NLROWS*CH];
__device__ float g_x   [NLROWS*CH];
__device__ float g_mem [NSROWS*CH];
__device__ float g_ck  [NSROWS*CH];
__device__ float g_cv  [NSROWS*CH];
__device__ float g_h   [NLROWS*HID];
__device__ float g_h2  [NLROWS*HID];
__device__ float g_kv  [NB*NH*DH*DH];
__device__ float g_ksum[NB*NH*DH];

// ---------------- LayerNorm (row of 256), optional y2 = y + addp ----------------
__global__ void ln_kernel(const float* __restrict__ x, const float* __restrict__ g,
                          const float* __restrict__ b, const float* __restrict__ addp,
                          float* __restrict__ y, float* __restrict__ y2)
{
    int row = blockIdx.x, tid = threadIdx.x;
    size_t base = (size_t)row * CH;
    float v = x[base + tid];
    float s1 = v, s2 = v * v;
    #pragma unroll
    for (int off = 16; off > 0; off >>= 1) {
        s1 += __shfl_xor_sync(0xffffffffu, s1, off);
        s2 += __shfl_xor_sync(0xffffffffu, s2, off);
    }
    __shared__ float r1[8], r2[8];
    int warp = tid >> 5, lane = tid & 31;
    if (lane == 0) { r1[warp] = s1; r2[warp] = s2; }
    __syncthreads();
    float t1 = 0.f, t2 = 0.f;
    #pragma unroll
    for (int w = 0; w < 8; w++) { t1 += r1[w]; t2 += r2[w]; }
    float mean = t1 * (1.f / CH);
    float var  = t2 * (1.f / CH) - mean * mean;
    float inv  = rsqrtf(var + 1e-5f);
    float out  = (v - mean) * inv * g[tid] + b[tid];
    y[base + tid] = out;
    if (y2) y2[base + tid] = out + addp[base + tid];
}

// ---------------- SGEMM: Y[M,OUT] = X[M,K] @ W[K,OUT] (+bias)(+epilogue) ----------------
// EPI 0: +bias ; EPI 1: elu(z)+1 ; EPI 2: +bias +res
template<int EPI>
__global__ void sgemm_k(const float* __restrict__ X, const float* __restrict__ W,
                        const float* __restrict__ bias, const float* __restrict__ res,
                        float* __restrict__ Y, int M, int K, int OUT)
{
    __shared__ float Xs[16][68];
    __shared__ float Ws[16][64];
    int tid = threadIdx.x;            // 256
    int tx = tid & 15, ty = tid >> 4;
    int row0 = blockIdx.y * 64, col0 = blockIdx.x * 64;
    float acc[4][4] = {};
    for (int k0 = 0; k0 < K; k0 += 16) {
        {
            int r = tid >> 2;             // 0..63
            int q = (tid & 3) * 4;        // 0,4,8,12
            float4 xv = *(const float4*)&X[(size_t)(row0 + r) * K + k0 + q];
            Xs[q + 0][r] = xv.x; Xs[q + 1][r] = xv.y;
            Xs[q + 2][r] = xv.z; Xs[q + 3][r] = xv.w;
        }
        {
            int kk = tid >> 4;            // 0..15
            int j  = (tid & 15) * 4;
            *(float4*)&Ws[kk][j] = *(const float4*)&W[(size_t)(k0 + kk) * OUT + col0 + j];
        }
        __syncthreads();
        #pragma unroll
        for (int kk = 0; kk < 16; kk++) {
            float4 a = *(const float4*)&Xs[kk][ty * 4];
            float4 b = *(const float4*)&Ws[kk][tx * 4];
            float ar[4] = {a.x, a.y, a.z, a.w};
            float br[4] = {b.x, b.y, b.z, b.w};
            #pragma unroll
            for (int i = 0; i < 4; i++)
                #pragma unroll
                for (int j = 0; j < 4; j++)
                    acc[i][j] += ar[i] * br[j];
        }
        __syncthreads();
    }
    #pragma unroll
    for (int i = 0; i < 4; i++) {
        int row = row0 + ty * 4 + i;
        #pragma unroll
        for (int j = 0; j < 4; j++) {
            int col = col0 + tx * 4 + j;
            float z = acc[i][j] + (bias ? bias[col] : 0.f);
            float out;
            if (EPI == 1) out = (z > 0.f) ? (z + 1.f) : __expf(z);
            else if (EPI == 2) out = z + res[(size_t)row * OUT + col];
            else out = z;
            Y[(size_t)row * OUT + col] = out;
        }
    }
}

// ---------------- zero KV stats ----------------
__global__ void zero_stats()
{
    int i = blockIdx.x * blockDim.x + threadIdx.x;
    if (i < NB*NH*DH*DH) g_kv[i] = 0.f;
    if (i < NB*NH*DH)    g_ksum[i] = 0.f;
}

// ---------------- linear-attn KV/Ksum (deterministic, one block per (n,h)) ----------------
__global__ void kv_accum()
{
    int nh = blockIdx.x;            // 0..31
    int n = nh >> 3, h = nh & 7;
    int tid = threadIdx.x;          // 1024
    int d = tid >> 5, vv = tid & 31;
    __shared__ float sk[64][32], sv[64][32];
    float acc = 0.f, ks = 0.f;
    for (int c0 = 0; c0 < LQ; c0 += 64) {
        __syncthreads();
        #pragma unroll
        for (int it = 0; it < 2; it++) {
            int idx = tid + it * 1024;      // 0..2047
            int s = idx >> 5, dd = idx & 31;
            size_t gbase = (size_t)(n * LQ + c0 + s) * CH + h * DH + dd;
            sk[s][dd] = g_k[gbase];
            sv[s][dd] = g_v[gbase];
        }
        __syncthreads();
        #pragma unroll
        for (int s = 0; s < 64; s++) {
            float kd = sk[s][d];
            acc += kd * sv[s][vv];
            ks  += kd;
        }
    }
    g_kv[(size_t)nh * (DH*DH) + d * DH + vv] = acc;   // (1/L and *L cancel exactly)
    if (vv == 0) g_ksum[nh * DH + d] = ks;
}

// ---------------- linear-attn output ----------------
__global__ void lin_out()
{
    int row = blockIdx.x;                 // n*L + l
    int n = row >> 11;
    int tid = threadIdx.x;                // 256
    int h = tid >> 5, lane = tid & 31;
    __shared__ float qsh[CH];
    qsh[tid] = g_q[(size_t)row * CH + tid];
    __syncthreads();
    int nh = n * NH + h;
    float z = qsh[h * DH + lane] * g_ksum[nh * DH + lane];
    #pragma unroll
    for (int off = 16; off > 0; off >>= 1) z += __shfl_xor_sync(0xffffffffu, z, off);
    float zinv = 1.f / (z + 1e-6f);
    const float* kvp = g_kv + (size_t)nh * (DH*DH);
    float acc = 0.f;
    #pragma unroll
    for (int dd = 0; dd < DH; dd++) acc += qsh[h * DH + dd] * kvp[dd * DH + lane];
    g_lao[(size_t)row * CH + tid] = acc * zinv;
}

// ---------------- mem = memory + pos_embed (broadcast over batch) ----------------
__global__ void mem_add(const float* __restrict__ memory, const float* __restrict__ pos)
{
    int i4 = blockIdx.x * blockDim.x + threadIdx.x;    // float4 index
    const int PER_N = SK * CH / 4;                     // 1048576/4
    int p4 = i4 % PER_N;
    float4 a = ((const float4*)memory)[i4];
    float4 b = ((const float4*)pos)[p4];
    a.x += b.x; a.y += b.y; a.z += b.z; a.w += b.w;
    ((float4*)g_mem)[i4] = a;
}

// ---------------- flash attention (fp32): 64q x 64s tiles, D=32 ----------------
__global__ void flash_attn()
{
    __shared__ float Qs[32][68];
    __shared__ float Ks[32][68];
    __shared__ float Vs[64][34];
    __shared__ float Ps[64][68];
    int tid = threadIdx.x;               // 256
    int tx = tid & 15, ty = tid >> 4;
    int qb = blockIdx.x * 64;
    int h = blockIdx.y, n = blockIdx.z;
    const float scale = 0.17677669529663687f;  // 32^-0.5

    #pragma unroll
    for (int it = 0; it < 8; it++) {
        int idx = tid + it * 256;         // 0..2047
        int r = idx >> 5, d = idx & 31;
        Qs[d][r] = g_cq[(size_t)(n * LQ + qb + r) * CH + h * DH + d] * scale;
    }

    float m[4], l[4], o[4][2];
    #pragma unroll
    for (int i = 0; i < 4; i++) { m[i] = -1e30f; l[i] = 0.f; o[i][0] = 0.f; o[i][1] = 0.f; }

    for (int sb = 0; sb < SK; sb += 64) {
        __syncthreads();   // previous PV done (also orders first-iter Q load below)
        #pragma unroll
        for (int it = 0; it < 8; it++) {
            int idx = tid + it * 256;
            int s = idx >> 5, d = idx & 31;
            size_t gb = (size_t)(n * SK + sb + s) * CH + h * DH + d;
            Ks[d][s] = g_ck[gb];
            Vs[s][d] = g_cv[gb];
        }
        __syncthreads();

        float sc[4][4] = {};
        #pragma unroll
        for (int d = 0; d < 32; d++) {
            float4 a = *(const float4*)&Qs[d][ty * 4];
            float4 b = *(const float4*)&Ks[d][tx * 4];
            float ar[4] = {a.x, a.y, a.z, a.w};
            float br[4] = {b.x, b.y, b.z, b.w};
            #pragma unroll
            for (int i = 0; i < 4; i++)
                #pragma unroll
                for (int j = 0; j < 4; j++)
                    sc[i][j] += ar[i] * br[j];
        }

        #pragma unroll
        for (int i = 0; i < 4; i++) {
            float rm = fmaxf(fmaxf(sc[i][0], sc[i][1]), fmaxf(sc[i][2], sc[i][3]));
            #pragma unroll
            for (int off = 1; off < 16; off <<= 1)
                rm = fmaxf(rm, __shfl_xor_sync(0xffffffffu, rm, off));
            float mnew = fmaxf(m[i], rm);
            float corr = __expf(m[i] - mnew);
            float p0 = __expf(sc[i][0] - mnew);
            float p1 = __expf(sc[i][1] - mnew);
            float p2 = __expf(sc[i][2] - mnew);
            float p3 = __expf(sc[i][3] - mnew);
            float rs = (p0 + p1) + (p2 + p3);
            #pragma unroll
            for (int off = 1; off < 16; off <<= 1)
                rs += __shfl_xor_sync(0xffffffffu, rs, off);
            l[i] = l[i] * corr + rs;
            m[i] = mnew;
            o[i][0] *= corr; o[i][1] *= corr;
            float4 pv; pv.x = p0; pv.y = p1; pv.z = p2; pv.w = p3;
            *(float4*)&Ps[ty * 4 + i][tx * 4] = pv;
        }
        __syncthreads();

        #pragma unroll 4
        for (int s = 0; s < 64; s++) {
            float2 vvv = *(const float2*)&Vs[s][tx * 2];
            #pragma unroll
            for (int i = 0; i < 4; i++) {
                float p = Ps[ty * 4 + i][s];
                o[i][0] += p * vvv.x;
                o[i][1] += p * vvv.y;
            }
        }
    }

    #pragma unroll
    for (int i = 0; i < 4; i++) {
        float inv = 1.f / l[i];
        size_t ob = (size_t)(n * LQ + qb + ty * 4 + i) * CH + h * DH + tx * 2;
        g_co[ob + 0] = o[i][0] * inv;
        g_co[ob + 1] = o[i][1] * inv;
    }
}

// ---------------- depthwise conv3 (along L) + bias + exact gelu ----------------
__global__ void conv_gelu(const float* __restrict__ dwk, const float* __restrict__ dwb)
{
    int i = blockIdx.x * blockDim.x + threadIdx.x;   // NLROWS*HID threads
    int c = i & (HID - 1);
    int l = (i >> 10) & (LQ - 1);
    float k0 = dwk[c * 9 + 1];   // kh=0, kw=1
    float k1 = dwk[c * 9 + 4];   // kh=1, kw=1
    float k2 = dwk[c * 9 + 7];   // kh=2, kw=1
    float v = g_h[i] * k1;
    if (l > 0)      v += g_h[i - HID] * k0;
    if (l < LQ - 1) v += g_h[i + HID] * k2;
    v += dwb[c];
    // exact gelu
    float out = 0.5f * v * (1.f + erff(v * 0.70710678118654752f));
    g_h2[i] = out;
}

// ---------------- host ----------------
extern "C" void kernel_launch(void* const* d_in, const int* in_sizes, int n_in,
                              void* d_out, int out_size)
{
    const float* tgt      = (const float*)d_in[0];
    const float* memory   = (const float*)d_in[1];
    const float* tgt_pos  = (const float*)d_in[2];
    const float* pos_emb  = (const float*)d_in[3];
    const float* ln1_g = (const float*)d_in[4],  *ln1_b = (const float*)d_in[5];
    const float* ln2_g = (const float*)d_in[6],  *ln2_b = (const float*)d_in[7];
    const float* ln3_g = (const float*)d_in[8],  *ln3_b = (const float*)d_in[9];
    const float* wq = (const float*)d_in[10], *bq = (const float*)d_in[11];
    const float* wk = (const float*)d_in[12], *bk = (const float*)d_in[13];
    const float* wv = (const float*)d_in[14], *bv = (const float*)d_in[15];
    const float* w_merge = (const float*)d_in[16];
    const float* cwq = (const float*)d_in[17], *cbq = (const float*)d_in[18];
    const float* cwk = (const float*)d_in[19], *cbk = (const float*)d_in[20];
    const float* cwv = (const float*)d_in[21], *cbv = (const float*)d_in[22];
    const float* cwo = (const float*)d_in[23], *cbo = (const float*)d_in[24];
    const float* mw1 = (const float*)d_in[25], *mb1 = (const float*)d_in[26];
    const float* dwk = (const float*)d_in[27], *dwb = (const float*)d_in[28];
    const float* mw2 = (const float*)d_in[29], *mb2 = (const float*)d_in[30];
    float* out = (float*)d_out;

    float *p_tgt2, *p_qk, *p_q, *p_k, *p_v, *p_lao, *p_t1, *p_cq, *p_co, *p_t2, *p_x;
    float *p_mem, *p_ck, *p_cv, *p_h, *p_h2;
    cudaGetSymbolAddress((void**)&p_tgt2, g_tgt2);
    cudaGetSymbolAddress((void**)&p_qk,   g_qk);
    cudaGetSymbolAddress((void**)&p_q,    g_q);
    cudaGetSymbolAddress((void**)&p_k,    g_k);
    cudaGetSymbolAddress((void**)&p_v,    g_v);
    cudaGetSymbolAddress((void**)&p_lao,  g_lao);
    cudaGetSymbolAddress((void**)&p_t1,   g_t1);
    cudaGetSymbolAddress((void**)&p_cq,   g_cq);
    cudaGetSymbolAddress((void**)&p_co,   g_co);
    cudaGetSymbolAddress((void**)&p_t2,   g_t2);
    cudaGetSymbolAddress((void**)&p_x,    g_x);
    cudaGetSymbolAddress((void**)&p_mem,  g_mem);
    cudaGetSymbolAddress((void**)&p_ck,   g_ck);
    cudaGetSymbolAddress((void**)&p_cv,   g_cv);
    cudaGetSymbolAddress((void**)&p_h,    g_h);
    cudaGetSymbolAddress((void**)&p_h2,   g_h2);

    dim3 g64_256(CH / 64, NLROWS / 64);        // (4,128)
    dim3 g64_1024(HID / 64, NLROWS / 64);      // (16,128)
    dim3 g64_mem(CH / 64, NSROWS / 64);        // (4,256)

    // ---- self attention (linear attention) ----
    ln_kernel<<<NLROWS, 256>>>(tgt, ln1_g, ln1_b, tgt_pos, p_tgt2, p_qk);
    sgemm_k<1><<<g64_256, 256>>>(p_qk,   wq, bq, nullptr, p_q, NLROWS, CH, CH);   // Q=elu+1
    sgemm_k<1><<<g64_256, 256>>>(p_qk,   wk, bk, nullptr, p_k, NLROWS, CH, CH);   // K=elu+1
    sgemm_k<0><<<g64_256, 256>>>(p_tgt2, wv, bv, nullptr, p_v, NLROWS, CH, CH);
    zero_stats<<<132, 256>>>();
    kv_accum<<<NB * NH, 1024>>>();
    lin_out<<<NLROWS, 256>>>();
    sgemm_k<2><<<g64_256, 256>>>(p_lao, w_merge, nullptr, tgt, p_t1, NLROWS, CH, CH);

    // ---- cross attention ----
    ln_kernel<<<NLROWS, 256>>>(p_t1, ln2_g, ln2_b, nullptr, p_tgt2, nullptr);
    mem_add<<<NSROWS * CH / 4 / 256, 256>>>(memory, pos_emb);
    sgemm_k<0><<<g64_256, 256>>>(p_tgt2, cwq, cbq, nullptr, p_cq, NLROWS, CH, CH);
    sgemm_k<0><<<g64_mem, 256>>>(p_mem,  cwk, cbk, nullptr, p_ck, NSROWS, CH, CH);
    sgemm_k<0><<<g64_mem, 256>>>(p_mem,  cwv, cbv, nullptr, p_cv, NSROWS, CH, CH);
    flash_attn<<<dim3(LQ / 64, NH, NB), 256>>>();
    sgemm_k<2><<<g64_256, 256>>>(p_co, cwo, cbo, p_t1, p_t2, NLROWS, CH, CH);

    // ---- MLP ----
    ln_kernel<<<NLROWS, 256>>>(p_t2, ln3_g, ln3_b, nullptr, p_x, nullptr);
    sgemm_k<0><<<g64_1024, 256>>>(p_x, mw1, mb1, nullptr, p_h, NLROWS, CH, HID);
    conv_gelu<<<NLROWS * HID / 256, 256>>>(dwk, dwb);
    sgemm_k<2><<<g64_256, 256>>>(p_h2, mw2, mb2, p_t2, out, NLROWS, HID, CH);
}

// round 2
// speedup vs baseline: 2.5955x; 2.5955x over previous
#include <cuda_runtime.h>
#include <cuda_bf16.h>
#include <math.h>
#include <stdint.h>

#define NB 4
#define LQ 2048
#define SK 4096
#define CH 256
#define NH 8
#define DH 32
#define HID 1024
#define NLROWS (NB*LQ)      // 8192
#define NSROWS (NB*SK)      // 16384

// ---------------- scratch (device globals; no runtime alloc) ----------------
__device__ float g_tgt2[NLROWS*CH];
__device__ float g_qk  [NLROWS*CH];
__device__ float g_q   [NLROWS*CH];
__device__ float g_k   [NLROWS*CH];
__device__ float g_v   [NLROWS*CH];
__device__ float g_lao [NLROWS*CH];
__device__ float g_t1  [NLROWS*CH];
__device__ float g_co  [NLROWS*CH];
__device__ float g_t2  [NLROWS*CH];
__device__ float g_x   [NLROWS*CH];
__device__ float g_mem [NSROWS*CH];
__device__ float g_h   [NLROWS*HID];
__device__ float g_h2  [NLROWS*HID];
__device__ float g_kv  [NB*NH*DH*DH];
__device__ float g_ksum[NB*NH*DH];
__device__ __nv_bfloat16 g_cqb[NLROWS*CH];
__device__ __nv_bfloat16 g_ckb[NSROWS*CH];
__device__ __nv_bfloat16 g_cvb[NSROWS*CH];

// ---------------- mma helpers ----------------
__device__ __forceinline__ void mma_tf32(float* c, uint32_t a0, uint32_t a1, uint32_t a2, uint32_t a3,
                                         uint32_t b0, uint32_t b1)
{
    asm volatile("mma.sync.aligned.m16n8k8.row.col.f32.tf32.tf32.f32 "
                 "{%0,%1,%2,%3}, {%4,%5,%6,%7}, {%8,%9}, {%0,%1,%2,%3};"
                 : "+f"(c[0]), "+f"(c[1]), "+f"(c[2]), "+f"(c[3])
                 : "r"(a0), "r"(a1), "r"(a2), "r"(a3), "r"(b0), "r"(b1));
}

__device__ __forceinline__ void mma_bf16(float* c, uint32_t a0, uint32_t a1, uint32_t a2, uint32_t a3,
                                         uint32_t b0, uint32_t b1)
{
    asm volatile("mma.sync.aligned.m16n8k16.row.col.f32.bf16.bf16.f32 "
                 "{%0,%1,%2,%3}, {%4,%5,%6,%7}, {%8,%9}, {%0,%1,%2,%3};"
                 : "+f"(c[0]), "+f"(c[1]), "+f"(c[2]), "+f"(c[3])
                 : "r"(a0), "r"(a1), "r"(a2), "r"(a3), "r"(b0), "r"(b1));
}

__device__ __forceinline__ float tf32r(float x)
{
    uint32_t u;
    asm("cvt.rna.tf32.f32 %0, %1;" : "=r"(u) : "f"(x));
    return __uint_as_float(u);
}

__device__ __forceinline__ uint32_t pack_bf16(float lo, float hi)
{
    __nv_bfloat162 t = __float22bfloat162_rn(make_float2(lo, hi));
    return *(uint32_t*)&t;
}

// ---------------- LayerNorm (row of 256), optional y2 = y + addp ----------------
__global__ void ln_kernel(const float* __restrict__ x, const float* __restrict__ g,
                          const float* __restrict__ b, const float* __restrict__ addp,
                          float* __restrict__ y, float* __restrict__ y2)
{
    int row = blockIdx.x, tid = threadIdx.x;
    size_t base = (size_t)row * CH;
    float v = x[base + tid];
    float s1 = v, s2 = v * v;
    #pragma unroll
    for (int off = 16; off > 0; off >>= 1) {
        s1 += __shfl_xor_sync(0xffffffffu, s1, off);
        s2 += __shfl_xor_sync(0xffffffffu, s2, off);
    }
    __shared__ float r1[8], r2[8];
    int warp = tid >> 5, lane = tid & 31;
    if (lane == 0) { r1[warp] = s1; r2[warp] = s2; }
    __syncthreads();
    float t1 = 0.f, t2 = 0.f;
    #pragma unroll
    for (int w = 0; w < 8; w++) { t1 += r1[w]; t2 += r2[w]; }
    float mean = t1 * (1.f / CH);
    float var  = t2 * (1.f / CH) - mean * mean;
    float inv  = rsqrtf(var + 1e-5f);
    float out  = (v - mean) * inv * g[tid] + b[tid];
    y[base + tid] = out;
    if (y2) y2[base + tid] = out + addp[base + tid];
}

// ---------------- tf32 tensor-core GEMM: Y[M,N] = X[M,K] @ W[K,N] ----------------
// EPI 0: +bias ; EPI 1: elu(z)+1 ; EPI 2: +bias +res.  OUTBF: write bf16.
// BM=128, BN=64, BK=16, 256 threads (8 warps: 4m x 2n), warp tile 32x32.
template<int EPI, bool OUTBF>
__global__ void gemm_tf32(const float* __restrict__ X, const float* __restrict__ W,
                          const float* __restrict__ bias, const float* __restrict__ res,
                          void* __restrict__ Yv, int M, int K, int N)
{
    __shared__ float As[128][20];   // stride 20: conflict-free fragment loads
    __shared__ float Ws[16][72];    // stride 72: conflict-free fragment loads
    int tid = threadIdx.x;
    int lane = tid & 31, wid = tid >> 5;
    int qd = lane & 3, rg = lane >> 2;
    int wm = wid >> 1, wn = wid & 1;
    int row0 = blockIdx.y * 128, col0 = blockIdx.x * 64;

    float acc[2][4][4];
    #pragma unroll
    for (int mi = 0; mi < 2; mi++)
        #pragma unroll
        for (int nj = 0; nj < 4; nj++)
            #pragma unroll
            for (int e = 0; e < 4; e++) acc[mi][nj][e] = 0.f;

    for (int k0 = 0; k0 < K; k0 += 16) {
        #pragma unroll
        for (int i = 0; i < 2; i++) {
            int idx = tid + i * 256;       // 0..511
            int r = idx >> 2;
            int c = (idx & 3) * 4;
            float4 xv = *(const float4*)&X[(size_t)(row0 + r) * K + k0 + c];
            float4 tv = make_float4(tf32r(xv.x), tf32r(xv.y), tf32r(xv.z), tf32r(xv.w));
            *(float4*)&As[r][c] = tv;
        }
        {
            int k = tid >> 4;
            int c = (tid & 15) * 4;
            float4 wv = *(const float4*)&W[(size_t)(k0 + k) * N + col0 + c];
            float4 tv = make_float4(tf32r(wv.x), tf32r(wv.y), tf32r(wv.z), tf32r(wv.w));
            *(float4*)&Ws[k][c] = tv;
        }
        __syncthreads();
        #pragma unroll
        for (int ks = 0; ks < 16; ks += 8) {
            uint32_t a[2][4];
            #pragma unroll
            for (int mi = 0; mi < 2; mi++) {
                int r = wm * 32 + mi * 16 + rg;
                a[mi][0] = *(uint32_t*)&As[r    ][ks + qd];
                a[mi][1] = *(uint32_t*)&As[r + 8][ks + qd];
                a[mi][2] = *(uint32_t*)&As[r    ][ks + qd + 4];
                a[mi][3] = *(uint32_t*)&As[r + 8][ks + qd + 4];
            }
            #pragma unroll
            for (int nj = 0; nj < 4; nj++) {
                int cidx = wn * 32 + nj * 8 + rg;
                uint32_t b0 = *(uint32_t*)&Ws[ks + qd    ][cidx];
                uint32_t b1 = *(uint32_t*)&Ws[ks + qd + 4][cidx];
                mma_tf32(acc[0][nj], a[0][0], a[0][1], a[0][2], a[0][3], b0, b1);
                mma_tf32(acc[1][nj], a[1][0], a[1][1], a[1][2], a[1][3], b0, b1);
            }
        }
        __syncthreads();
    }

    #pragma unroll
    for (int mi = 0; mi < 2; mi++) {
        #pragma unroll
        for (int nj = 0; nj < 4; nj++) {
            int r = row0 + wm * 32 + mi * 16 + rg;
            int c = col0 + wn * 32 + nj * 8 + qd * 2;
            float b0v = bias ? bias[c] : 0.f;
            float b1v = bias ? bias[c + 1] : 0.f;
            #pragma unroll
            for (int half = 0; half < 2; half++) {
                int rr = r + half * 8;
                float z0 = acc[mi][nj][half * 2 + 0] + b0v;
                float z1 = acc[mi][nj][half * 2 + 1] + b1v;
                if (EPI == 1) {
                    z0 = (z0 > 0.f) ? (z0 + 1.f) : __expf(z0);
                    z1 = (z1 > 0.f) ? (z1 + 1.f) : __expf(z1);
                } else if (EPI == 2) {
                    const float2 rv = *(const float2*)&res[(size_t)rr * N + c];
                    z0 += rv.x; z1 += rv.y;
                }
                size_t off = (size_t)rr * N + c;
                if (OUTBF) {
                    __nv_bfloat162 o = __float22bfloat162_rn(make_float2(z0, z1));
                    *(__nv_bfloat162*)((__nv_bfloat16*)Yv + off) = o;
                } else {
                    *(float2*)((float*)Yv + off) = make_float2(z0, z1);
                }
            }
        }
    }
}

// ---------------- zero KV stats ----------------
__global__ void zero_stats()
{
    int i = blockIdx.x * blockDim.x + threadIdx.x;
    if (i < NB*NH*DH*DH) g_kv[i] = 0.f;
    if (i < NB*NH*DH)    g_ksum[i] = 0.f;
}

// ---------------- linear-attn KV/Ksum (deterministic, one block per (n,h)) ----------------
__global__ void kv_accum()
{
    int nh = blockIdx.x;            // 0..31
    int n = nh >> 3, h = nh & 7;
    int tid = threadIdx.x;          // 1024
    int d = tid >> 5, vv = tid & 31;
    __shared__ float sk[64][32], sv[64][32];
    float acc = 0.f, ks = 0.f;
    for (int c0 = 0; c0 < LQ; c0 += 64) {
        __syncthreads();
        #pragma unroll
        for (int it = 0; it < 2; it++) {
            int idx = tid + it * 1024;
            int s = idx >> 5, dd = idx & 31;
            size_t gbase = (size_t)(n * LQ + c0 + s) * CH + h * DH + dd;
            sk[s][dd] = g_k[gbase];
            sv[s][dd] = g_v[gbase];
        }
        __syncthreads();
        #pragma unroll
        for (int s = 0; s < 64; s++) {
            float kd = sk[s][d];
            acc += kd * sv[s][vv];
            ks  += kd;
        }
    }
    g_kv[(size_t)nh * (DH*DH) + d * DH + vv] = acc;
    if (vv == 0) g_ksum[nh * DH + d] = ks;
}

// ---------------- linear-attn output ----------------
__global__ void lin_out()
{
    int row = blockIdx.x;
    int n = row >> 11;
    int tid = threadIdx.x;
    int h = tid >> 5, lane = tid & 31;
    __shared__ float qsh[CH];
    qsh[tid] = g_q[(size_t)row * CH + tid];
    __syncthreads();
    int nh = n * NH + h;
    float z = qsh[h * DH + lane] * g_ksum[nh * DH + lane];
    #pragma unroll
    for (int off = 16; off > 0; off >>= 1) z += __shfl_xor_sync(0xffffffffu, z, off);
    float zinv = 1.f / (z + 1e-6f);
    const float* kvp = g_kv + (size_t)nh * (DH*DH);
    float acc = 0.f;
    #pragma unroll
    for (int dd = 0; dd < DH; dd++) acc += qsh[h * DH + dd] * kvp[dd * DH + lane];
    g_lao[(size_t)row * CH + tid] = acc * zinv;
}

// ---------------- mem = memory + pos_embed (broadcast over batch) ----------------
__global__ void mem_add(const float* __restrict__ memory, const float* __restrict__ pos)
{
    int i4 = blockIdx.x * blockDim.x + threadIdx.x;
    const int PER_N = SK * CH / 4;
    int p4 = i4 % PER_N;
    float4 a = ((const float4*)memory)[i4];
    float4 b = ((const float4*)pos)[p4];
    a.x += b.x; a.y += b.y; a.z += b.z; a.w += b.w;
    ((float4*)g_mem)[i4] = a;
}

// ---------------- flash attention, bf16 mma: 64q x 64s tiles, D=32 ----------------
// 128 threads (4 warps), each warp owns 16 q rows.
__global__ void flash_attn_mma()
{
    __shared__ __nv_bfloat16 Qs[64][36];
    __shared__ __nv_bfloat16 Ks[64][36];
    __shared__ __nv_bfloat16 Vt[32][72];
    int tid = threadIdx.x;
    int lane = tid & 31, wid = tid >> 5;
    int qd = lane & 3, rg = lane >> 2;
    int qb = blockIdx.x * 64, h = blockIdx.y, n = blockIdx.z;
    const float scale = 0.17677669529663687f;   // 32^-0.5

    // load Q tile (bf16x2 loads)
    #pragma unroll
    for (int i = 0; i < 8; i++) {
        int idx = tid + i * 128;          // 0..1023
        int r = idx >> 4, dp = idx & 15;
        uint32_t v = *(const uint32_t*)&g_cqb[(size_t)(n * LQ + qb + r) * CH + h * DH + dp * 2];
        *(uint32_t*)&Qs[r][dp * 2] = v;
    }

    float m0 = -1e30f, m1 = -1e30f, l0 = 0.f, l1 = 0.f;
    float o[4][4] = {};
    int r0 = wid * 16 + rg;

    for (int sb = 0; sb < SK; sb += 64) {
        __syncthreads();
        #pragma unroll
        for (int i = 0; i < 8; i++) {
            int idx = tid + i * 128;
            int s = idx >> 4, dp = idx & 15;
            size_t gb = (size_t)(n * SK + sb + s) * CH + h * DH + dp * 2;
            uint32_t kvv = *(const uint32_t*)&g_ckb[gb];
            *(uint32_t*)&Ks[s][dp * 2] = kvv;
            uint32_t vvv = *(const uint32_t*)&g_cvb[gb];
            Vt[dp * 2    ][s] = ((__nv_bfloat16*)&vvv)[0];
            Vt[dp * 2 + 1][s] = ((__nv_bfloat16*)&vvv)[1];
        }
        __syncthreads();

        // S = Q @ K^T  (per warp: 16x64, 8 n-frags, 2 k-steps)
        float sc[8][4];
        #pragma unroll
        for (int j = 0; j < 8; j++)
            #pragma unroll
            for (int e = 0; e < 4; e++) sc[j][e] = 0.f;
        #pragma unroll
        for (int ks = 0; ks < 2; ks++) {
            uint32_t a0 = *(uint32_t*)&Qs[r0    ][ks * 16 + qd * 2];
            uint32_t a1 = *(uint32_t*)&Qs[r0 + 8][ks * 16 + qd * 2];
            uint32_t a2 = *(uint32_t*)&Qs[r0    ][ks * 16 + qd * 2 + 8];
            uint32_t a3 = *(uint32_t*)&Qs[r0 + 8][ks * 16 + qd * 2 + 8];
            #pragma unroll
            for (int j = 0; j < 8; j++) {
                uint32_t b0 = *(uint32_t*)&Ks[j * 8 + rg][ks * 16 + qd * 2];
                uint32_t b1 = *(uint32_t*)&Ks[j * 8 + rg][ks * 16 + qd * 2 + 8];
                mma_bf16(sc[j], a0, a1, a2, a3, b0, b1);
            }
        }

        // online softmax (scale folded into exp)
        float rm0 = -1e30f, rm1 = -1e30f;
        #pragma unroll
        for (int j = 0; j < 8; j++) {
            rm0 = fmaxf(rm0, fmaxf(sc[j][0], sc[j][1]));
            rm1 = fmaxf(rm1, fmaxf(sc[j][2], sc[j][3]));
        }
        rm0 = fmaxf(rm0, __shfl_xor_sync(0xffffffffu, rm0, 1));
        rm0 = fmaxf(rm0, __shfl_xor_sync(0xffffffffu, rm0, 2));
        rm1 = fmaxf(rm1, __shfl_xor_sync(0xffffffffu, rm1, 1));
        rm1 = fmaxf(rm1, __shfl_xor_sync(0xffffffffu, rm1, 2));
        float mn0 = fmaxf(m0, rm0), mn1 = fmaxf(m1, rm1);
        float corr0 = __expf((m0 - mn0) * scale);
        float corr1 = __expf((m1 - mn1) * scale);
        float s0 = 0.f, s1 = 0.f;
        #pragma unroll
        for (int j = 0; j < 8; j++) {
            sc[j][0] = __expf((sc[j][0] - mn0) * scale);
            sc[j][1] = __expf((sc[j][1] - mn0) * scale);
            sc[j][2] = __expf((sc[j][2] - mn1) * scale);
            sc[j][3] = __expf((sc[j][3] - mn1) * scale);
            s0 += sc[j][0] + sc[j][1];
            s1 += sc[j][2] + sc[j][3];
        }
        s0 += __shfl_xor_sync(0xffffffffu, s0, 1);
        s0 += __shfl_xor_sync(0xffffffffu, s0, 2);
        s1 += __shfl_xor_sync(0xffffffffu, s1, 1);
        s1 += __shfl_xor_sync(0xffffffffu, s1, 2);
        l0 = l0 * corr0 + s0;
        l1 = l1 * corr1 + s1;
        m0 = mn0; m1 = mn1;
        #pragma unroll
        for (int dj = 0; dj < 4; dj++) {
            o[dj][0] *= corr0; o[dj][1] *= corr0;
            o[dj][2] *= corr1; o[dj][3] *= corr1;
        }

        // O += P @ V   (P repacked from S c-frags to A-frags)
        #pragma unroll
        for (int t = 0; t < 4; t++) {
            uint32_t pa0 = pack_bf16(sc[2 * t    ][0], sc[2 * t    ][1]);
            uint32_t pa1 = pack_bf16(sc[2 * t    ][2], sc[2 * t    ][3]);
            uint32_t pa2 = pack_bf16(sc[2 * t + 1][0], sc[2 * t + 1][1]);
            uint32_t pa3 = pack_bf16(sc[2 * t + 1][2], sc[2 * t + 1][3]);
            #pragma unroll
            for (int dj = 0; dj < 4; dj++) {
                uint32_t b0 = *(uint32_t*)&Vt[dj * 8 + rg][t * 16 + qd * 2];
                uint32_t b1 = *(uint32_t*)&Vt[dj * 8 + rg][t * 16 + qd * 2 + 8];
                mma_bf16(o[dj], pa0, pa1, pa2, pa3, b0, b1);
            }
        }
    }

    float inv0 = 1.f / l0, inv1 = 1.f / l1;
    #pragma unroll
    for (int dj = 0; dj < 4; dj++) {
        size_t b0 = (size_t)(n * LQ + qb + r0    ) * CH + h * DH + dj * 8 + qd * 2;
        size_t b1 = (size_t)(n * LQ + qb + r0 + 8) * CH + h * DH + dj * 8 + qd * 2;
        *(float2*)&g_co[b0] = make_float2(o[dj][0] * inv0, o[dj][1] * inv0);
        *(float2*)&g_co[b1] = make_float2(o[dj][2] * inv1, o[dj][3] * inv1);
    }
}

// ---------------- depthwise conv3 (along L) + bias + exact gelu ----------------
__global__ void conv_gelu(const float* __restrict__ dwk, const float* __restrict__ dwb)
{
    int i = blockIdx.x * blockDim.x + threadIdx.x;
    int c = i & (HID - 1);
    int l = (i >> 10) & (LQ - 1);
    float k0 = dwk[c * 9 + 1];
    float k1 = dwk[c * 9 + 4];
    float k2 = dwk[c * 9 + 7];
    float v = g_h[i] * k1;
    if (l > 0)      v += g_h[i - HID] * k0;
    if (l < LQ - 1) v += g_h[i + HID] * k2;
    v += dwb[c];
    float out = 0.5f * v * (1.f + erff(v * 0.70710678118654752f));
    g_h2[i] = out;
}

// ---------------- host ----------------
extern "C" void kernel_launch(void* const* d_in, const int* in_sizes, int n_in,
                              void* d_out, int out_size)
{
    const float* tgt      = (const float*)d_in[0];
    const float* memory   = (const float*)d_in[1];
    const float* tgt_pos  = (const float*)d_in[2];
    const float* pos_emb  = (const float*)d_in[3];
    const float* ln1_g = (const float*)d_in[4],  *ln1_b = (const float*)d_in[5];
    const float* ln2_g = (const float*)d_in[6],  *ln2_b = (const float*)d_in[7];
    const float* ln3_g = (const float*)d_in[8],  *ln3_b = (const float*)d_in[9];
    const float* wq = (const float*)d_in[10], *bq = (const float*)d_in[11];
    const float* wk = (const float*)d_in[12], *bk = (const float*)d_in[13];
    const float* wv = (const float*)d_in[14], *bv = (const float*)d_in[15];
    const float* w_merge = (const float*)d_in[16];
    const float* cwq = (const float*)d_in[17], *cbq = (const float*)d_in[18];
    const float* cwk = (const float*)d_in[19], *cbk = (const float*)d_in[20];
    const float* cwv = (const float*)d_in[21], *cbv = (const float*)d_in[22];
    const float* cwo = (const float*)d_in[23], *cbo = (const float*)d_in[24];
    const float* mw1 = (const float*)d_in[25], *mb1 = (const float*)d_in[26];
    const float* dwk = (const float*)d_in[27], *dwb = (const float*)d_in[28];
    const float* mw2 = (const float*)d_in[29], *mb2 = (const float*)d_in[30];
    float* out = (float*)d_out;

    float *p_tgt2, *p_qk, *p_q, *p_k, *p_v, *p_lao, *p_t1, *p_co, *p_t2, *p_x;
    float *p_mem, *p_h, *p_h2;
    __nv_bfloat16 *p_cqb, *p_ckb, *p_cvb;
    cudaGetSymbolAddress((void**)&p_tgt2, g_tgt2);
    cudaGetSymbolAddress((void**)&p_qk,   g_qk);
    cudaGetSymbolAddress((void**)&p_q,    g_q);
    cudaGetSymbolAddress((void**)&p_k,    g_k);
    cudaGetSymbolAddress((void**)&p_v,    g_v);
    cudaGetSymbolAddress((void**)&p_lao,  g_lao);
    cudaGetSymbolAddress((void**)&p_t1,   g_t1);
    cudaGetSymbolAddress((void**)&p_co,   g_co);
    cudaGetSymbolAddress((void**)&p_t2,   g_t2);
    cudaGetSymbolAddress((void**)&p_x,    g_x);
    cudaGetSymbolAddress((void**)&p_mem,  g_mem);
    cudaGetSymbolAddress((void**)&p_h,    g_h);
    cudaGetSymbolAddress((void**)&p_h2,   g_h2);
    cudaGetSymbolAddress((void**)&p_cqb,  g_cqb);
    cudaGetSymbolAddress((void**)&p_ckb,  g_ckb);
    cudaGetSymbolAddress((void**)&p_cvb,  g_cvb);

    dim3 gq(CH / 64, NLROWS / 128);        // (4,64)
    dim3 gmem2(CH / 64, NSROWS / 128);     // (4,128)
    dim3 gm1(HID / 64, NLROWS / 128);      // (16,64)

    // ---- self attention (linear attention) ----
    ln_kernel<<<NLROWS, 256>>>(tgt, ln1_g, ln1_b, tgt_pos, p_tgt2, p_qk);
    gemm_tf32<1, false><<<gq, 256>>>(p_qk,   wq, bq, nullptr, p_q, NLROWS, CH, CH);
    gemm_tf32<1, false><<<gq, 256>>>(p_qk,   wk, bk, nullptr, p_k, NLROWS, CH, CH);
    gemm_tf32<0, false><<<gq, 256>>>(p_tgt2, wv, bv, nullptr, p_v, NLROWS, CH, CH);
    zero_stats<<<132, 256>>>();
    kv_accum<<<NB * NH, 1024>>>();
    lin_out<<<NLROWS, 256>>>();
    gemm_tf32<2, false><<<gq, 256>>>(p_lao, w_merge, nullptr, tgt, p_t1, NLROWS, CH, CH);

    // ---- cross attention ----
    ln_kernel<<<NLROWS, 256>>>(p_t1, ln2_g, ln2_b, nullptr, p_tgt2, nullptr);
    mem_add<<<NSROWS * CH / 4 / 256, 256>>>(memory, pos_emb);
    gemm_tf32<0, true><<<gq,    256>>>(p_tgt2, cwq, cbq, nullptr, p_cqb, NLROWS, CH, CH);
    gemm_tf32<0, true><<<gmem2, 256>>>(p_mem,  cwk, cbk, nullptr, p_ckb, NSROWS, CH, CH);
    gemm_tf32<0, true><<<gmem2, 256>>>(p_mem,  cwv, cbv, nullptr, p_cvb, NSROWS, CH, CH);
    flash_attn_mma<<<dim3(LQ / 64, NH, NB), 128>>>();
    gemm_tf32<2, false><<<gq, 256>>>(p_co, cwo, cbo, p_t1, p_t2, NLROWS, CH, CH);

    // ---- MLP ----
    ln_kernel<<<NLROWS, 256>>>(p_t2, ln3_g, ln3_b, nullptr, p_x, nullptr);
    gemm_tf32<0, false><<<gm1, 256>>>(p_x, mw1, mb1, nullptr, p_h, NLROWS, CH, HID);
    conv_gelu<<<NLROWS * HID / 256, 256>>>(dwk, dwb);
    gemm_tf32<2, false><<<gq, 256>>>(p_h2, mw2, mb2, p_t2, out, NLROWS, HID, CH);
}

// round 3
// speedup vs baseline: 3.5814x; 1.3799x over previous
#include <cuda_runtime.h>
#include <cuda_bf16.h>
#include <math.h>
#include <stdint.h>

#define NB 4
#define LQ 2048
#define SK 4096
#define CH 256
#define NH 8
#define DH 32
#define HID 1024
#define NLROWS (NB*LQ)      // 8192
#define NSROWS (NB*SK)      // 16384

// ---------------- scratch (device globals; no runtime alloc) ----------------
__device__ float g_q   [NLROWS*CH];
__device__ float g_k   [NLROWS*CH];
__device__ float g_v   [NLROWS*CH];
__device__ float g_t1  [NLROWS*CH];
__device__ float g_t2  [NLROWS*CH];
__device__ float g_h   [NLROWS*HID];
__device__ float g_kv  [NB*NH*DH*DH];
__device__ float g_ksum[NB*NH*DH];
__device__ float g_kvp [NB*NH*8*DH*DH];
__device__ float g_ksp [NB*NH*8*DH];

__device__ __nv_bfloat16 g_xb1 [NLROWS*CH];   // ln outputs (tgt2 / ln2 / ln3)
__device__ __nv_bfloat16 g_xb2 [NLROWS*CH];   // qk = tgt2 + tgt_pos
__device__ __nv_bfloat16 g_laob[NLROWS*CH];
__device__ __nv_bfloat16 g_memb[NSROWS*CH];
__device__ __nv_bfloat16 g_cqb [NLROWS*CH];
__device__ __nv_bfloat16 g_ckb [NSROWS*CH];
__device__ __nv_bfloat16 g_cvb [NSROWS*CH];
__device__ __nv_bfloat16 g_cob [NLROWS*CH];
__device__ __nv_bfloat16 g_h2b [NLROWS*HID];
__device__ __nv_bfloat16 g_wts [8*CH*CH + CH*HID + HID*CH];   // transposed bf16 weights

// offsets into g_wts
#define WT_WQ   0
#define WT_WK   (1*CH*CH)
#define WT_WV   (2*CH*CH)
#define WT_WM   (3*CH*CH)
#define WT_CWQ  (4*CH*CH)
#define WT_CWK  (5*CH*CH)
#define WT_CWV  (6*CH*CH)
#define WT_CWO  (7*CH*CH)
#define WT_MW1  (8*CH*CH)
#define WT_MW2  (8*CH*CH + CH*HID)

// ---------------- helpers ----------------
__device__ __forceinline__ void mma_bf16(float* c, uint32_t a0, uint32_t a1, uint32_t a2, uint32_t a3,
                                         uint32_t b0, uint32_t b1)
{
    asm volatile("mma.sync.aligned.m16n8k16.row.col.f32.bf16.bf16.f32 "
                 "{%0,%1,%2,%3}, {%4,%5,%6,%7}, {%8,%9}, {%0,%1,%2,%3};"
                 : "+f"(c[0]), "+f"(c[1]), "+f"(c[2]), "+f"(c[3])
                 : "r"(a0), "r"(a1), "r"(a2), "r"(a3), "r"(b0), "r"(b1));
}

__device__ __forceinline__ uint32_t pack_bf16(float lo, float hi)
{
    __nv_bfloat162 t = __float22bfloat162_rn(make_float2(lo, hi));
    return *(uint32_t*)&t;
}

__device__ __forceinline__ uint32_t saddr(const void* p)
{
    return (uint32_t)__cvta_generic_to_shared(p);
}

#define CP16(dst, src) asm volatile("cp.async.cg.shared.global [%0], [%1], 16;" :: "r"(dst), "l"(src))
#define CP_COMMIT()    asm volatile("cp.async.commit_group;")
#define CP_WAIT0()     asm volatile("cp.async.wait_group 0;")
#define CP_WAIT1()     asm volatile("cp.async.wait_group 1;")

// ---------------- weight transpose + bf16 convert: Wt[N,K] = bf16(W[K,N]) ----------------
__global__ void wtrans(const float* __restrict__ W, __nv_bfloat16* __restrict__ Wt, int K, int N)
{
    __shared__ float t[32][33];
    int n0 = blockIdx.x * 32, k0 = blockIdx.y * 32;
    int tx = threadIdx.x, ty = threadIdx.y;   // (32,8)
    #pragma unroll
    for (int i = 0; i < 4; i++)
        t[ty + i * 8][tx] = W[(size_t)(k0 + ty + i * 8) * N + n0 + tx];
    __syncthreads();
    #pragma unroll
    for (int i = 0; i < 4; i++)
        Wt[(size_t)(n0 + ty + i * 8) * K + k0 + tx] = __float2bfloat16(t[tx][ty + i * 8]);
}

// ---------------- LayerNorm: bf16 outputs (y, optional y2=y+addp) ----------------
__global__ void ln_kernel(const float* __restrict__ x, const float* __restrict__ g,
                          const float* __restrict__ b, const float* __restrict__ addp,
                          __nv_bfloat16* __restrict__ y, __nv_bfloat16* __restrict__ y2)
{
    int row = blockIdx.x, tid = threadIdx.x;
    size_t base = (size_t)row * CH;
    float v = x[base + tid];
    float s1 = v, s2 = v * v;
    #pragma unroll
    for (int off = 16; off > 0; off >>= 1) {
        s1 += __shfl_xor_sync(0xffffffffu, s1, off);
        s2 += __shfl_xor_sync(0xffffffffu, s2, off);
    }
    __shared__ float r1[8], r2[8];
    int warp = tid >> 5, lane = tid & 31;
    if (lane == 0) { r1[warp] = s1; r2[warp] = s2; }
    __syncthreads();
    float t1 = 0.f, t2 = 0.f;
    #pragma unroll
    for (int w = 0; w < 8; w++) { t1 += r1[w]; t2 += r2[w]; }
    float mean = t1 * (1.f / CH);
    float var  = t2 * (1.f / CH) - mean * mean;
    float inv  = rsqrtf(var + 1e-5f);
    float out  = (v - mean) * inv * g[tid] + b[tid];
    y[base + tid] = __float2bfloat16(out);
    if (y2) y2[base + tid] = __float2bfloat16(out + addp[base + tid]);
}

// ---------------- bf16 tensor-core GEMM: Y[M,N] = X[M,K] @ Wt[N,K]^T ----------------
// EPI 0: +bias ; EPI 1: elu(z)+1 ; EPI 2: +bias +res.  OUTBF: write bf16.
// BM=128, BN=64, BK=32, 2-stage cp.async pipeline, 256 threads (8 warps 4m x 2n).
template<int EPI, bool OUTBF>
__global__ void gemm_bf16(const __nv_bfloat16* __restrict__ X, const __nv_bfloat16* __restrict__ Wt,
                          const float* __restrict__ bias, const float* __restrict__ res,
                          void* __restrict__ Yv, int M, int K, int N)
{
    __shared__ __nv_bfloat16 As[2][128][40];
    __shared__ __nv_bfloat16 Bs[2][64][40];
    int tid = threadIdx.x;
    int lane = tid & 31, wid = tid >> 5;
    int qd = lane & 3, rg = lane >> 2;
    int wm = wid >> 1, wn = wid & 1;
    int row0 = blockIdx.y * 128, col0 = blockIdx.x * 64;

    float acc[2][4][4];
    #pragma unroll
    for (int mi = 0; mi < 2; mi++)
        #pragma unroll
        for (int nj = 0; nj < 4; nj++)
            #pragma unroll
            for (int e = 0; e < 4; e++) acc[mi][nj][e] = 0.f;

    int ar0 = tid >> 2, as0 = tid & 3;       // A chunk 0 (of 2) and B chunk
    int ar1 = (tid + 256) >> 2, as1 = as0;   // A chunk 1

    const int T = K / 32;
    // prologue: stage 0
    {
        CP16(saddr(&As[0][ar0][as0 * 8]), X + (size_t)(row0 + ar0) * K + as0 * 8);
        CP16(saddr(&As[0][ar1][as1 * 8]), X + (size_t)(row0 + ar1) * K + as1 * 8);
        CP16(saddr(&Bs[0][tid >> 2][(tid & 3) * 8]), Wt + (size_t)(col0 + (tid >> 2)) * K + (tid & 3) * 8);
        CP_COMMIT();
    }

    for (int kt = 0; kt < T; kt++) {
        if (kt + 1 < T) {
            int st = (kt + 1) & 1, k0 = (kt + 1) * 32;
            CP16(saddr(&As[st][ar0][as0 * 8]), X + (size_t)(row0 + ar0) * K + k0 + as0 * 8);
            CP16(saddr(&As[st][ar1][as1 * 8]), X + (size_t)(row0 + ar1) * K + k0 + as1 * 8);
            CP16(saddr(&Bs[st][tid >> 2][(tid & 3) * 8]), Wt + (size_t)(col0 + (tid >> 2)) * K + k0 + (tid & 3) * 8);
            CP_COMMIT();
            CP_WAIT1();
        } else {
            CP_WAIT0();
        }
        __syncthreads();
        int st = kt & 1;
        #pragma unroll
        for (int ks = 0; ks < 2; ks++) {
            uint32_t a[2][4];
            #pragma unroll
            for (int mi = 0; mi < 2; mi++) {
                int r = wm * 32 + mi * 16 + rg;
                a[mi][0] = *(uint32_t*)&As[st][r    ][ks * 16 + qd * 2];
                a[mi][1] = *(uint32_t*)&As[st][r + 8][ks * 16 + qd * 2];
                a[mi][2] = *(uint32_t*)&As[st][r    ][ks * 16 + qd * 2 + 8];
                a[mi][3] = *(uint32_t*)&As[st][r + 8][ks * 16 + qd * 2 + 8];
            }
            #pragma unroll
            for (int nj = 0; nj < 4; nj++) {
                int c = wn * 32 + nj * 8 + rg;
                uint32_t b0 = *(uint32_t*)&Bs[st][c][ks * 16 + qd * 2];
                uint32_t b1 = *(uint32_t*)&Bs[st][c][ks * 16 + qd * 2 + 8];
                mma_bf16(acc[0][nj], a[0][0], a[0][1], a[0][2], a[0][3], b0, b1);
                mma_bf16(acc[1][nj], a[1][0], a[1][1], a[1][2], a[1][3], b0, b1);
            }
        }
        __syncthreads();
    }

    #pragma unroll
    for (int mi = 0; mi < 2; mi++) {
        #pragma unroll
        for (int nj = 0; nj < 4; nj++) {
            int r = row0 + wm * 32 + mi * 16 + rg;
            int c = col0 + wn * 32 + nj * 8 + qd * 2;
            float b0v = bias ? bias[c] : 0.f;
            float b1v = bias ? bias[c + 1] : 0.f;
            #pragma unroll
            for (int half = 0; half < 2; half++) {
                int rr = r + half * 8;
                float z0 = acc[mi][nj][half * 2 + 0] + b0v;
                float z1 = acc[mi][nj][half * 2 + 1] + b1v;
                if (EPI == 1) {
                    z0 = (z0 > 0.f) ? (z0 + 1.f) : __expf(z0);
                    z1 = (z1 > 0.f) ? (z1 + 1.f) : __expf(z1);
                } else if (EPI == 2) {
                    const float2 rv = *(const float2*)&res[(size_t)rr * N + c];
                    z0 += rv.x; z1 += rv.y;
                }
                size_t off = (size_t)rr * N + c;
                if (OUTBF) {
                    __nv_bfloat162 o = __float22bfloat162_rn(make_float2(z0, z1));
                    *(__nv_bfloat162*)((__nv_bfloat16*)Yv + off) = o;
                } else {
                    *(float2*)((float*)Yv + off) = make_float2(z0, z1);
                }
            }
        }
    }
}

// ---------------- linear-attn KV/Ksum partials: grid (32 nh, 8 parts) ----------------
__global__ void kv_accum()
{
    int nh = blockIdx.x, part = blockIdx.y;
    int n = nh >> 3, h = nh & 7;
    int tid = threadIdx.x;          // 1024
    int d = tid >> 5, vv = tid & 31;
    __shared__ float sk[64][32], sv[64][32];
    float acc = 0.f, ks = 0.f;
    int base = part * 256;
    for (int c0 = base; c0 < base + 256; c0 += 64) {
        __syncthreads();
        #pragma unroll
        for (int it = 0; it < 2; it++) {
            int idx = tid + it * 1024;
            int s = idx >> 5, dd = idx & 31;
            size_t gbase = (size_t)(n * LQ + c0 + s) * CH + h * DH + dd;
            sk[s][dd] = g_k[gbase];
            sv[s][dd] = g_v[gbase];
        }
        __syncthreads();
        #pragma unroll
        for (int s = 0; s < 64; s++) {
            float kd = sk[s][d];
            acc += kd * sv[s][vv];
            ks  += kd;
        }
    }
    g_kvp[(size_t)((nh << 3) + part) * (DH*DH) + d * DH + vv] = acc;
    if (vv == 0) g_ksp[((nh << 3) + part) * DH + d] = ks;
}

__global__ void kv_reduce()
{
    int nh = blockIdx.x, i = threadIdx.x;    // 32 blocks x 1024
    float s = 0.f;
    #pragma unroll
    for (int p = 0; p < 8; p++) s += g_kvp[(size_t)((nh << 3) + p) * (DH*DH) + i];
    g_kv[(size_t)nh * (DH*DH) + i] = s;
    if (i < DH) {
        float ks = 0.f;
        #pragma unroll
        for (int p = 0; p < 8; p++) ks += g_ksp[((nh << 3) + p) * DH + i];
        g_ksum[nh * DH + i] = ks;
    }
}

// ---------------- linear-attn output (bf16 out) ----------------
__global__ void lin_out()
{
    int row = blockIdx.x;
    int n = row >> 11;
    int tid = threadIdx.x;
    int h = tid >> 5, lane = tid & 31;
    __shared__ float qsh[CH];
    qsh[tid] = g_q[(size_t)row * CH + tid];
    __syncthreads();
    int nh = n * NH + h;
    float z = qsh[h * DH + lane] * g_ksum[nh * DH + lane];
    #pragma unroll
    for (int off = 16; off > 0; off >>= 1) z += __shfl_xor_sync(0xffffffffu, z, off);
    float zinv = 1.f / (z + 1e-6f);
    const float* kvp = g_kv + (size_t)nh * (DH*DH);
    float acc = 0.f;
    #pragma unroll
    for (int dd = 0; dd < DH; dd++) acc += qsh[h * DH + dd] * kvp[dd * DH + lane];
    g_laob[(size_t)row * CH + tid] = __float2bfloat16(acc * zinv);
}

// ---------------- mem = bf16(memory + pos_embed) ----------------
__global__ void mem_add(const float* __restrict__ memory, const float* __restrict__ pos)
{
    int i4 = blockIdx.x * blockDim.x + threadIdx.x;
    const int PER_N = SK * CH / 4;
    int p4 = i4 % PER_N;
    float4 a = ((const float4*)memory)[i4];
    float4 b = ((const float4*)pos)[p4];
    uint32_t lo = pack_bf16(a.x + b.x, a.y + b.y);
    uint32_t hi = pack_bf16(a.z + b.z, a.w + b.w);
    ((uint2*)g_memb)[i4] = make_uint2(lo, hi);
}

// ---------------- flash attention: 128q x 64s tiles, 8 warps, D=32 ----------------
__global__ void flash_attn_mma()
{
    __shared__ __nv_bfloat16 Qs[128][36];
    __shared__ __nv_bfloat16 Ks[64][40];
    __shared__ __nv_bfloat16 Vt[32][72];
    int tid = threadIdx.x;               // 256
    int lane = tid & 31, wid = tid >> 5;
    int qd = lane & 3, rg = lane >> 2;
    int qb = blockIdx.x * 128, h = blockIdx.y, n = blockIdx.z;
    const float scale = 0.17677669529663687f;   // 32^-0.5

    // load Q tile
    #pragma unroll
    for (int i = 0; i < 8; i++) {
        int idx = tid + i * 256;          // 0..2047
        int r = idx >> 4, dp = idx & 15;
        uint32_t v = *(const uint32_t*)&g_cqb[(size_t)(n * LQ + qb + r) * CH + h * DH + dp * 2];
        *(uint32_t*)&Qs[r][dp * 2] = v;
    }

    float m0 = -1e30f, m1 = -1e30f, l0 = 0.f, l1 = 0.f;
    float o[4][4] = {};
    int r0 = wid * 16 + rg;

    for (int sb = 0; sb < SK; sb += 64) {
        __syncthreads();   // prior compute done (also orders Q writes on first iter)
        // K tile via cp.async
        {
            int r = tid >> 2, s = tid & 3;
            CP16(saddr(&Ks[r][s * 8]), g_ckb + (size_t)(n * SK + sb + r) * CH + h * DH + s * 8);
            CP_COMMIT();
        }
        // V tile: transpose in smem
        #pragma unroll
        for (int i = 0; i < 4; i++) {
            int idx = tid + i * 256;
            int s = idx >> 4, dp = idx & 15;
            uint32_t vvv = *(const uint32_t*)&g_cvb[(size_t)(n * SK + sb + s) * CH + h * DH + dp * 2];
            Vt[dp * 2    ][s] = ((__nv_bfloat16*)&vvv)[0];
            Vt[dp * 2 + 1][s] = ((__nv_bfloat16*)&vvv)[1];
        }
        CP_WAIT0();
        __syncthreads();

        // S = Q @ K^T  (per warp: 16x64)
        float sc[8][4];
        #pragma unroll
        for (int j = 0; j < 8; j++)
            #pragma unroll
            for (int e = 0; e < 4; e++) sc[j][e] = 0.f;
        #pragma unroll
        for (int ks = 0; ks < 2; ks++) {
            uint32_t a0 = *(uint32_t*)&Qs[r0    ][ks * 16 + qd * 2];
            uint32_t a1 = *(uint32_t*)&Qs[r0 + 8][ks * 16 + qd * 2];
            uint32_t a2 = *(uint32_t*)&Qs[r0    ][ks * 16 + qd * 2 + 8];
            uint32_t a3 = *(uint32_t*)&Qs[r0 + 8][ks * 16 + qd * 2 + 8];
            #pragma unroll
            for (int j = 0; j < 8; j++) {
                uint32_t b0 = *(uint32_t*)&Ks[j * 8 + rg][ks * 16 + qd * 2];
                uint32_t b1 = *(uint32_t*)&Ks[j * 8 + rg][ks * 16 + qd * 2 + 8];
                mma_bf16(sc[j], a0, a1, a2, a3, b0, b1);
            }
        }

        // online softmax (scale folded into exp)
        float rm0 = -1e30f, rm1 = -1e30f;
        #pragma unroll
        for (int j = 0; j < 8; j++) {
            rm0 = fmaxf(rm0, fmaxf(sc[j][0], sc[j][1]));
            rm1 = fmaxf(rm1, fmaxf(sc[j][2], sc[j][3]));
        }
        rm0 = fmaxf(rm0, __shfl_xor_sync(0xffffffffu, rm0, 1));
        rm0 = fmaxf(rm0, __shfl_xor_sync(0xffffffffu, rm0, 2));
        rm1 = fmaxf(rm1, __shfl_xor_sync(0xffffffffu, rm1, 1));
        rm1 = fmaxf(rm1, __shfl_xor_sync(0xffffffffu, rm1, 2));
        float mn0 = fmaxf(m0, rm0), mn1 = fmaxf(m1, rm1);
        float corr0 = __expf((m0 - mn0) * scale);
        float corr1 = __expf((m1 - mn1) * scale);
        float s0 = 0.f, s1 = 0.f;
        #pragma unroll
        for (int j = 0; j < 8; j++) {
            sc[j][0] = __expf((sc[j][0] - mn0) * scale);
            sc[j][1] = __expf((sc[j][1] - mn0) * scale);
            sc[j][2] = __expf((sc[j][2] - mn1) * scale);
            sc[j][3] = __expf((sc[j][3] - mn1) * scale);
            s0 += sc[j][0] + sc[j][1];
            s1 += sc[j][2] + sc[j][3];
        }
        s0 += __shfl_xor_sync(0xffffffffu, s0, 1);
        s0 += __shfl_xor_sync(0xffffffffu, s0, 2);
        s1 += __shfl_xor_sync(0xffffffffu, s1, 1);
        s1 += __shfl_xor_sync(0xffffffffu, s1, 2);
        l0 = l0 * corr0 + s0;
        l1 = l1 * corr1 + s1;
        m0 = mn0; m1 = mn1;
        #pragma unroll
        for (int dj = 0; dj < 4; dj++) {
            o[dj][0] *= corr0; o[dj][1] *= corr0;
            o[dj][2] *= corr1; o[dj][3] *= corr1;
        }

        // O += P @ V
        #pragma unroll
        for (int t = 0; t < 4; t++) {
            uint32_t pa0 = pack_bf16(sc[2 * t    ][0], sc[2 * t    ][1]);
            uint32_t pa1 = pack_bf16(sc[2 * t    ][2], sc[2 * t    ][3]);
            uint32_t pa2 = pack_bf16(sc[2 * t + 1][0], sc[2 * t + 1][1]);
            uint32_t pa3 = pack_bf16(sc[2 * t + 1][2], sc[2 * t + 1][3]);
            #pragma unroll
            for (int dj = 0; dj < 4; dj++) {
                uint32_t b0 = *(uint32_t*)&Vt[dj * 8 + rg][t * 16 + qd * 2];
                uint32_t b1 = *(uint32_t*)&Vt[dj * 8 + rg][t * 16 + qd * 2 + 8];
                mma_bf16(o[dj], pa0, pa1, pa2, pa3, b0, b1);
            }
        }
    }

    float inv0 = 1.f / l0, inv1 = 1.f / l1;
    #pragma unroll
    for (int dj = 0; dj < 4; dj++) {
        size_t b0 = (size_t)(n * LQ + qb + r0    ) * CH + h * DH + dj * 8 + qd * 2;
        size_t b1 = (size_t)(n * LQ + qb + r0 + 8) * CH + h * DH + dj * 8 + qd * 2;
        *(__nv_bfloat162*)&g_cob[b0] = __float22bfloat162_rn(make_float2(o[dj][0] * inv0, o[dj][1] * inv0));
        *(__nv_bfloat162*)&g_cob[b1] = __float22bfloat162_rn(make_float2(o[dj][2] * inv1, o[dj][3] * inv1));
    }
}

// ---------------- depthwise conv3 (along L) + bias + exact gelu (bf16 out) ----------------
__global__ void conv_gelu(const float* __restrict__ dwk, const float* __restrict__ dwb)
{
    int i = blockIdx.x * blockDim.x + threadIdx.x;
    int c = i & (HID - 1);
    int l = (i >> 10) & (LQ - 1);
    float k0 = dwk[c * 9 + 1];
    float k1 = dwk[c * 9 + 4];
    float k2 = dwk[c * 9 + 7];
    float v = g_h[i] * k1;
    if (l > 0)      v += g_h[i - HID] * k0;
    if (l < LQ - 1) v += g_h[i + HID] * k2;
    v += dwb[c];
    float out = 0.5f * v * (1.f + erff(v * 0.70710678118654752f));
    g_h2b[i] = __float2bfloat16(out);
}

// ---------------- host ----------------
extern "C" void kernel_launch(void* const* d_in, const int* in_sizes, int n_in,
                              void* d_out, int out_size)
{
    const float* tgt      = (const float*)d_in[0];
    const float* memory   = (const float*)d_in[1];
    const float* tgt_pos  = (const float*)d_in[2];
    const float* pos_emb  = (const float*)d_in[3];
    const float* ln1_g = (const float*)d_in[4],  *ln1_b = (const float*)d_in[5];
    const float* ln2_g = (const float*)d_in[6],  *ln2_b = (const float*)d_in[7];
    const float* ln3_g = (const float*)d_in[8],  *ln3_b = (const float*)d_in[9];
    const float* wq = (const float*)d_in[10], *bq = (const float*)d_in[11];
    const float* wk = (const float*)d_in[12], *bk = (const float*)d_in[13];
    const float* wv = (const float*)d_in[14], *bv = (const float*)d_in[15];
    const float* w_merge = (const float*)d_in[16];
    const float* cwq = (const float*)d_in[17], *cbq = (const float*)d_in[18];
    const float* cwk = (const float*)d_in[19], *cbk = (const float*)d_in[20];
    const float* cwv = (const float*)d_in[21], *cbv = (const float*)d_in[22];
    const float* cwo = (const float*)d_in[23], *cbo = (const float*)d_in[24];
    const float* mw1 = (const float*)d_in[25], *mb1 = (const float*)d_in[26];
    const float* dwk = (const float*)d_in[27], *dwb = (const float*)d_in[28];
    const float* mw2 = (const float*)d_in[29], *mb2 = (const float*)d_in[30];
    float* out = (float*)d_out;

    float *p_q, *p_k, *p_v, *p_t1, *p_t2, *p_h;
    __nv_bfloat16 *p_xb1, *p_xb2, *p_laob, *p_memb, *p_cqb, *p_ckb, *p_cvb, *p_cob, *p_h2b, *p_wts;
    cudaGetSymbolAddress((void**)&p_q,    g_q);
    cudaGetSymbolAddress((void**)&p_k,    g_k);
    cudaGetSymbolAddress((void**)&p_v,    g_v);
    cudaGetSymbolAddress((void**)&p_t1,   g_t1);
    cudaGetSymbolAddress((void**)&p_t2,   g_t2);
    cudaGetSymbolAddress((void**)&p_h,    g_h);
    cudaGetSymbolAddress((void**)&p_xb1,  g_xb1);
    cudaGetSymbolAddress((void**)&p_xb2,  g_xb2);
    cudaGetSymbolAddress((void**)&p_laob, g_laob);
    cudaGetSymbolAddress((void**)&p_memb, g_memb);
    cudaGetSymbolAddress((void**)&p_cqb,  g_cqb);
    cudaGetSymbolAddress((void**)&p_ckb,  g_ckb);
    cudaGetSymbolAddress((void**)&p_cvb,  g_cvb);
    cudaGetSymbolAddress((void**)&p_cob,  g_cob);
    cudaGetSymbolAddress((void**)&p_h2b,  g_h2b);
    cudaGetSymbolAddress((void**)&p_wts,  g_wts);

    // ---- weight transposes (bf16 [N,K]) ----
    dim3 tb(32, 8);
    wtrans<<<dim3(CH/32, CH/32), tb>>>(wq,      p_wts + WT_WQ,  CH, CH);
    wtrans<<<dim3(CH/32, CH/32), tb>>>(wk,      p_wts + WT_WK,  CH, CH);
    wtrans<<<dim3(CH/32, CH/32), tb>>>(wv,      p_wts + WT_WV,  CH, CH);
    wtrans<<<dim3(CH/32, CH/32), tb>>>(w_merge, p_wts + WT_WM,  CH, CH);
    wtrans<<<dim3(CH/32, CH/32), tb>>>(cwq,     p_wts + WT_CWQ, CH, CH);
    wtrans<<<dim3(CH/32, CH/32), tb>>>(cwk,     p_wts + WT_CWK, CH, CH);
    wtrans<<<dim3(CH/32, CH/32), tb>>>(cwv,     p_wts + WT_CWV, CH, CH);
    wtrans<<<dim3(CH/32, CH/32), tb>>>(cwo,     p_wts + WT_CWO, CH, CH);
    wtrans<<<dim3(HID/32, CH/32), tb>>>(mw1,    p_wts + WT_MW1, CH, HID);
    wtrans<<<dim3(CH/32, HID/32), tb>>>(mw2,    p_wts + WT_MW2, HID, CH);

    dim3 gq(CH / 64, NLROWS / 128);        // (4,64)
    dim3 gmem2(CH / 64, NSROWS / 128);     // (4,128)
    dim3 gm1(HID / 64, NLROWS / 128);      // (16,64)

    // ---- self attention (linear attention) ----
    ln_kernel<<<NLROWS, 256>>>(tgt, ln1_g, ln1_b, tgt_pos, p_xb1, p_xb2);
    gemm_bf16<1, false><<<gq, 256>>>(p_xb2, p_wts + WT_WQ, bq, nullptr, p_q, NLROWS, CH, CH);
    gemm_bf16<1, false><<<gq, 256>>>(p_xb2, p_wts + WT_WK, bk, nullptr, p_k, NLROWS, CH, CH);
    gemm_bf16<0, false><<<gq, 256>>>(p_xb1, p_wts + WT_WV, bv, nullptr, p_v, NLROWS, CH, CH);
    kv_accum<<<dim3(NB * NH, 8), 1024>>>();
    kv_reduce<<<NB * NH, 1024>>>();
    lin_out<<<NLROWS, 256>>>();
    gemm_bf16<2, false><<<gq, 256>>>(p_laob, p_wts + WT_WM, nullptr, tgt, p_t1, NLROWS, CH, CH);

    // ---- cross attention ----
    ln_kernel<<<NLROWS, 256>>>(p_t1, ln2_g, ln2_b, nullptr, p_xb1, nullptr);
    mem_add<<<NSROWS * CH / 4 / 256, 256>>>(memory, pos_emb);
    gemm_bf16<0, true><<<gq,    256>>>(p_xb1,  p_wts + WT_CWQ, cbq, nullptr, p_cqb, NLROWS, CH, CH);
    gemm_bf16<0, true><<<gmem2, 256>>>(p_memb, p_wts + WT_CWK, cbk, nullptr, p_ckb, NSROWS, CH, CH);
    gemm_bf16<0, true><<<gmem2, 256>>>(p_memb, p_wts + WT_CWV, cbv, nullptr, p_cvb, NSROWS, CH, CH);
    flash_attn_mma<<<dim3(LQ / 128, NH, NB), 256>>>();
    gemm_bf16<2, false><<<gq, 256>>>(p_cob, p_wts + WT_CWO, cbo, p_t1, p_t2, NLROWS, CH, CH);

    // ---- MLP ----
    ln_kernel<<<NLROWS, 256>>>(p_t2, ln3_g, ln3_b, nullptr, p_xb1, nullptr);
    gemm_bf16<0, false><<<gm1, 256>>>(p_xb1, p_wts + WT_MW1, mb1, nullptr, p_h, NLROWS, CH, HID);
    conv_gelu<<<NLROWS * HID / 256, 256>>>(dwk, dwb);
    gemm_bf16<2, false><<<gq, 256>>>(p_h2b, p_wts + WT_MW2, mb2, p_t2, out, NLROWS, HID, CH);
}

// round 4
// speedup vs baseline: 4.2769x; 1.1942x over previous
#include <cuda_runtime.h>
#include <cuda_bf16.h>
#include <math.h>
#include <stdint.h>

#define NB 4
#define LQ 2048
#define SK 4096
#define CH 256
#define NH 8
#define DH 32
#define HID 1024
#define NLROWS (NB*LQ)      // 8192
#define NSROWS (NB*SK)      // 16384

// ---------------- scratch (device globals; no runtime alloc) ----------------
__device__ float g_q   [NLROWS*CH];
__device__ float g_k   [NLROWS*CH];
__device__ float g_v   [NLROWS*CH];
__device__ float g_t1  [NLROWS*CH];
__device__ float g_t2  [NLROWS*CH];
__device__ float g_kv  [NB*NH*DH*DH];
__device__ float g_ksum[NB*NH*DH];
__device__ float g_kvp [NB*NH*8*DH*DH];
__device__ float g_ksp [NB*NH*8*DH];

__device__ __nv_bfloat16 g_xb1 [NLROWS*CH];
__device__ __nv_bfloat16 g_xb2 [NLROWS*CH];
__device__ __nv_bfloat16 g_laob[NLROWS*CH];
__device__ __nv_bfloat16 g_memb[NSROWS*CH];
__device__ __nv_bfloat16 g_cqb [NLROWS*CH];
__device__ __nv_bfloat16 g_ckb [NSROWS*CH];
__device__ __nv_bfloat16 g_cvb [NSROWS*CH];
__device__ __nv_bfloat16 g_cvt [NB*NH*DH*SK];    // V transposed per (n,h): [d][s]
__device__ __nv_bfloat16 g_cob [NLROWS*CH];
__device__ __nv_bfloat16 g_hb  [NLROWS*HID];
__device__ __nv_bfloat16 g_h2b [NLROWS*HID];
__device__ __nv_bfloat16 g_wts [8*CH*CH + CH*HID + HID*CH];

#define WT_WQ   0
#define WT_WK   (1*CH*CH)
#define WT_WV   (2*CH*CH)
#define WT_WM   (3*CH*CH)
#define WT_CWQ  (4*CH*CH)
#define WT_CWK  (5*CH*CH)
#define WT_CWV  (6*CH*CH)
#define WT_CWO  (7*CH*CH)
#define WT_MW1  (8*CH*CH)
#define WT_MW2  (8*CH*CH + CH*HID)

// ---------------- helpers ----------------
__device__ __forceinline__ void mma_bf16(float* c, uint32_t a0, uint32_t a1, uint32_t a2, uint32_t a3,
                                         uint32_t b0, uint32_t b1)
{
    asm volatile("mma.sync.aligned.m16n8k16.row.col.f32.bf16.bf16.f32 "
                 "{%0,%1,%2,%3}, {%4,%5,%6,%7}, {%8,%9}, {%0,%1,%2,%3};"
                 : "+f"(c[0]), "+f"(c[1]), "+f"(c[2]), "+f"(c[3])
                 : "r"(a0), "r"(a1), "r"(a2), "r"(a3), "r"(b0), "r"(b1));
}

__device__ __forceinline__ uint32_t pack_bf16(float lo, float hi)
{
    __nv_bfloat162 t = __float22bfloat162_rn(make_float2(lo, hi));
    return *(uint32_t*)&t;
}

__device__ __forceinline__ uint32_t saddr(const void* p)
{
    return (uint32_t)__cvta_generic_to_shared(p);
}

#define CP16(dst, src) asm volatile("cp.async.cg.shared.global [%0], [%1], 16;" :: "r"(dst), "l"(src))
#define CP_COMMIT()    asm volatile("cp.async.commit_group;")
#define CP_WAIT0()     asm volatile("cp.async.wait_group 0;")
#define CP_WAIT1()     asm volatile("cp.async.wait_group 1;")

// ---------------- fused weight transpose: all 10 weights in one launch ----------------
struct WSrc { const float* p[10]; };

__global__ void wtrans_all(WSrc ws, __nv_bfloat16* __restrict__ dst)
{
    __shared__ float t[32][33];
    int bid = blockIdx.x;
    int w, kt, nt;
    if (bid < 512)       { w = bid >> 6;  int r = bid & 63;   kt = r >> 3; nt = r & 7;  }
    else if (bid < 768)  { w = 8;         int r = bid - 512;  kt = r >> 5; nt = r & 31; }
    else                 { w = 9;         int r = bid - 768;  kt = r >> 3; nt = r & 7;  }
    int Kd = (w == 9) ? 1024 : 256;
    int Nd = (w == 8) ? 1024 : 256;
    size_t doff = (w < 8) ? (size_t)w * (CH*CH) : (w == 8 ? (size_t)8*CH*CH : (size_t)8*CH*CH + CH*HID);
    const float* W = ws.p[w];
    __nv_bfloat16* Wt = dst + doff;
    int n0 = nt * 32, k0 = kt * 32;
    int tx = threadIdx.x, ty = threadIdx.y;   // (32,8)
    #pragma unroll
    for (int i = 0; i < 4; i++)
        t[ty + i * 8][tx] = W[(size_t)(k0 + ty + i * 8) * Nd + n0 + tx];
    __syncthreads();
    #pragma unroll
    for (int i = 0; i < 4; i++)
        Wt[(size_t)(n0 + ty + i * 8) * Kd + k0 + tx] = __float2bfloat16(t[tx][ty + i * 8]);
}

// ---------------- LayerNorm: bf16 outputs (y, optional y2=y+addp) ----------------
__global__ void ln_kernel(const float* __restrict__ x, const float* __restrict__ g,
                          const float* __restrict__ b, const float* __restrict__ addp,
                          __nv_bfloat16* __restrict__ y, __nv_bfloat16* __restrict__ y2)
{
    int row = blockIdx.x, tid = threadIdx.x;
    size_t base = (size_t)row * CH;
    float v = x[base + tid];
    float s1 = v, s2 = v * v;
    #pragma unroll
    for (int off = 16; off > 0; off >>= 1) {
        s1 += __shfl_xor_sync(0xffffffffu, s1, off);
        s2 += __shfl_xor_sync(0xffffffffu, s2, off);
    }
    __shared__ float r1[8], r2[8];
    int warp = tid >> 5, lane = tid & 31;
    if (lane == 0) { r1[warp] = s1; r2[warp] = s2; }
    __syncthreads();
    float t1 = 0.f, t2 = 0.f;
    #pragma unroll
    for (int w = 0; w < 8; w++) { t1 += r1[w]; t2 += r2[w]; }
    float mean = t1 * (1.f / CH);
    float var  = t2 * (1.f / CH) - mean * mean;
    float inv  = rsqrtf(var + 1e-5f);
    float out  = (v - mean) * inv * g[tid] + b[tid];
    y[base + tid] = __float2bfloat16(out);
    if (y2) y2[base + tid] = __float2bfloat16(out + addp[base + tid]);
}

// ---------------- bf16 tensor-core GEMM, 3-stage cp.async, single sync/iter ----------------
// Y[M,NOUT] (and Y2 if DUAL) = X[M,K] @ Wt[NWT,K]^T
// EPI 0: +bias ; EPI 1: elu(z)+1 ; EPI 2: +bias +res.  OUTBF: write bf16.
template<int EPI, bool OUTBF, bool DUAL>
__global__ void gemm_bf16(const __nv_bfloat16* __restrict__ X, const __nv_bfloat16* __restrict__ Wt,
                          const float* __restrict__ bias, const float* __restrict__ bias2,
                          const float* __restrict__ res,
                          void* __restrict__ Yv, void* __restrict__ Yv2,
                          int M, int K, int NOUT)
{
    __shared__ __nv_bfloat16 As[3][128][40];
    __shared__ __nv_bfloat16 Bs[3][64][40];
    int tid = threadIdx.x;
    int lane = tid & 31, wid = tid >> 5;
    int qd = lane & 3, rg = lane >> 2;
    int wm = wid >> 1, wn = wid & 1;
    int row0 = blockIdx.y * 128, col0 = blockIdx.x * 64;

    float acc[2][4][4];
    #pragma unroll
    for (int mi = 0; mi < 2; mi++)
        #pragma unroll
        for (int nj = 0; nj < 4; nj++)
            #pragma unroll
            for (int e = 0; e < 4; e++) acc[mi][nj][e] = 0.f;

    int ar = tid >> 2, ac = (tid & 3) * 8;     // A: 2 chunks per thread (rows ar, ar+64)
    int br = tid >> 2, bc = (tid & 3) * 8;     // B: 1 chunk per thread

    const int T = K / 32;
    // prologue: tiles 0 and 1
    #pragma unroll
    for (int pt = 0; pt < 2; pt++) {
        if (pt < T) {
            int k0 = pt * 32;
            CP16(saddr(&As[pt][ar     ][ac]), X  + (size_t)(row0 + ar     ) * K + k0 + ac);
            CP16(saddr(&As[pt][ar + 64][ac]), X  + (size_t)(row0 + ar + 64) * K + k0 + ac);
            CP16(saddr(&Bs[pt][br][bc]),      Wt + (size_t)(col0 + br     ) * K + k0 + bc);
        }
        CP_COMMIT();
    }

    for (int kt = 0; kt < T; kt++) {
        CP_WAIT1();
        __syncthreads();
        int st = kt % 3;
        #pragma unroll
        for (int ks = 0; ks < 2; ks++) {
            uint32_t a[2][4];
            #pragma unroll
            for (int mi = 0; mi < 2; mi++) {
                int r = wm * 32 + mi * 16 + rg;
                a[mi][0] = *(uint32_t*)&As[st][r    ][ks * 16 + qd * 2];
                a[mi][1] = *(uint32_t*)&As[st][r + 8][ks * 16 + qd * 2];
                a[mi][2] = *(uint32_t*)&As[st][r    ][ks * 16 + qd * 2 + 8];
                a[mi][3] = *(uint32_t*)&As[st][r + 8][ks * 16 + qd * 2 + 8];
            }
            #pragma unroll
            for (int nj = 0; nj < 4; nj++) {
                int c = wn * 32 + nj * 8 + rg;
                uint32_t b0 = *(uint32_t*)&Bs[st][c][ks * 16 + qd * 2];
                uint32_t b1 = *(uint32_t*)&Bs[st][c][ks * 16 + qd * 2 + 8];
                mma_bf16(acc[0][nj], a[0][0], a[0][1], a[0][2], a[0][3], b0, b1);
                mma_bf16(acc[1][nj], a[1][0], a[1][1], a[1][2], a[1][3], b0, b1);
            }
        }
        if (kt + 2 < T) {
            int st2 = (kt + 2) % 3, k0 = (kt + 2) * 32;
            CP16(saddr(&As[st2][ar     ][ac]), X  + (size_t)(row0 + ar     ) * K + k0 + ac);
            CP16(saddr(&As[st2][ar + 64][ac]), X  + (size_t)(row0 + ar + 64) * K + k0 + ac);
            CP16(saddr(&Bs[st2][br][bc]),      Wt + (size_t)(col0 + br     ) * K + k0 + bc);
        }
        CP_COMMIT();
    }

    #pragma unroll
    for (int mi = 0; mi < 2; mi++) {
        #pragma unroll
        for (int nj = 0; nj < 4; nj++) {
            int r = row0 + wm * 32 + mi * 16 + rg;
            int c = col0 + wn * 32 + nj * 8 + qd * 2;
            void* Yp = Yv;
            const float* bp = bias;
            int cc = c;
            if (DUAL && c >= NOUT) { Yp = Yv2; bp = bias2; cc = c - NOUT; }
            float b0v = bp ? bp[cc] : 0.f;
            float b1v = bp ? bp[cc + 1] : 0.f;
            #pragma unroll
            for (int half = 0; half < 2; half++) {
                int rr = r + half * 8;
                float z0 = acc[mi][nj][half * 2 + 0] + b0v;
                float z1 = acc[mi][nj][half * 2 + 1] + b1v;
                if (EPI == 1) {
                    z0 = (z0 > 0.f) ? (z0 + 1.f) : __expf(z0);
                    z1 = (z1 > 0.f) ? (z1 + 1.f) : __expf(z1);
                } else if (EPI == 2) {
                    const float2 rv = *(const float2*)&res[(size_t)rr * NOUT + cc];
                    z0 += rv.x; z1 += rv.y;
                }
                size_t off = (size_t)rr * NOUT + cc;
                if (OUTBF) {
                    *(__nv_bfloat162*)((__nv_bfloat16*)Yp + off) =
                        __float22bfloat162_rn(make_float2(z0, z1));
                } else {
                    *(float2*)((float*)Yp + off) = make_float2(z0, z1);
                }
            }
        }
    }
}

// ---------------- linear-attn KV/Ksum partials ----------------
__global__ void kv_accum()
{
    int nh = blockIdx.x, part = blockIdx.y;
    int n = nh >> 3, h = nh & 7;
    int tid = threadIdx.x;          // 1024
    int d = tid >> 5, vv = tid & 31;
    __shared__ float sk[64][32], sv[64][32];
    float acc = 0.f, ks = 0.f;
    int base = part * 256;
    for (int c0 = base; c0 < base + 256; c0 += 64) {
        __syncthreads();
        #pragma unroll
        for (int it = 0; it < 2; it++) {
            int idx = tid + it * 1024;
            int s = idx >> 5, dd = idx & 31;
            size_t gbase = (size_t)(n * LQ + c0 + s) * CH + h * DH + dd;
            sk[s][dd] = g_k[gbase];
            sv[s][dd] = g_v[gbase];
        }
        __syncthreads();
        #pragma unroll
        for (int s = 0; s < 64; s++) {
            float kd = sk[s][d];
            acc += kd * sv[s][vv];
            ks  += kd;
        }
    }
    g_kvp[(size_t)((nh << 3) + part) * (DH*DH) + d * DH + vv] = acc;
    if (vv == 0) g_ksp[((nh << 3) + part) * DH + d] = ks;
}

__global__ void kv_reduce()
{
    int nh = blockIdx.x, i = threadIdx.x;
    float s = 0.f;
    #pragma unroll
    for (int p = 0; p < 8; p++) s += g_kvp[(size_t)((nh << 3) + p) * (DH*DH) + i];
    g_kv[(size_t)nh * (DH*DH) + i] = s;
    if (i < DH) {
        float ks = 0.f;
        #pragma unroll
        for (int p = 0; p < 8; p++) ks += g_ksp[((nh << 3) + p) * DH + i];
        g_ksum[nh * DH + i] = ks;
    }
}

// ---------------- linear-attn output (bf16 out) ----------------
__global__ void lin_out()
{
    int row = blockIdx.x;
    int n = row >> 11;
    int tid = threadIdx.x;
    int h = tid >> 5, lane = tid & 31;
    __shared__ float qsh[CH];
    qsh[tid] = g_q[(size_t)row * CH + tid];
    __syncthreads();
    int nh = n * NH + h;
    float z = qsh[h * DH + lane] * g_ksum[nh * DH + lane];
    #pragma unroll
    for (int off = 16; off > 0; off >>= 1) z += __shfl_xor_sync(0xffffffffu, z, off);
    float zinv = 1.f / (z + 1e-6f);
    const float* kvp = g_kv + (size_t)nh * (DH*DH);
    float acc = 0.f;
    #pragma unroll
    for (int dd = 0; dd < DH; dd++) acc += qsh[h * DH + dd] * kvp[dd * DH + lane];
    g_laob[(size_t)row * CH + tid] = __float2bfloat16(acc * zinv);
}

// ---------------- mem = bf16(memory + pos_embed) ----------------
__global__ void mem_add(const float* __restrict__ memory, const float* __restrict__ pos)
{
    int i4 = blockIdx.x * blockDim.x + threadIdx.x;
    const int PER_N = SK * CH / 4;
    int p4 = i4 % PER_N;
    float4 a = ((const float4*)memory)[i4];
    float4 b = ((const float4*)pos)[p4];
    uint32_t lo = pack_bf16(a.x + b.x, a.y + b.y);
    uint32_t hi = pack_bf16(a.z + b.z, a.w + b.w);
    ((uint2*)g_memb)[i4] = make_uint2(lo, hi);
}

// ---------------- V transpose per (n,h): [s][d] -> [d][s] ----------------
__global__ void vtrans()
{
    __shared__ __nv_bfloat16 t[32][33];
    int s0 = blockIdx.x * 32;
    int nh = blockIdx.y;
    int n = nh >> 3, h = nh & 7;
    int tx = threadIdx.x, ty = threadIdx.y;   // (32,8)
    #pragma unroll
    for (int i = 0; i < 4; i++)
        t[ty + i * 8][tx] = g_cvb[(size_t)(n * SK + s0 + ty + i * 8) * CH + h * DH + tx];
    __syncthreads();
    #pragma unroll
    for (int i = 0; i < 4; i++)
        g_cvt[(size_t)(nh * DH + ty + i * 8) * SK + s0 + tx] = t[tx][ty + i * 8];
}

// ---------------- flash attention: 128q x 64s tiles, 8 warps, 3-stage cp.async ----------------
__global__ void flash_attn_mma()
{
    __shared__ __nv_bfloat16 Qs[128][36];
    __shared__ __nv_bfloat16 Ks[3][64][40];
    __shared__ __nv_bfloat16 Vs[3][32][72];
    int tid = threadIdx.x;               // 256
    int lane = tid & 31, wid = tid >> 5;
    int qd = lane & 3, rg = lane >> 2;
    int qb = blockIdx.x * 128, h = blockIdx.y, n = blockIdx.z;
    int nh = n * NH + h;
    const float scale = 0.17677669529663687f;   // 32^-0.5

    // load Q tile
    #pragma unroll
    for (int i = 0; i < 8; i++) {
        int idx = tid + i * 256;
        int r = idx >> 4, dp = idx & 15;
        uint32_t v = *(const uint32_t*)&g_cqb[(size_t)(n * LQ + qb + r) * CH + h * DH + dp * 2];
        *(uint32_t*)&Qs[r][dp * 2] = v;
    }

    // prologue: K/V tiles 0, 1
    int kr = tid >> 2, kc = (tid & 3) * 8;
    int vr = tid >> 3, vc = (tid & 7) * 8;
    const int T = SK / 64;
    #pragma unroll
    for (int pt = 0; pt < 2; pt++) {
        int sb = pt * 64;
        CP16(saddr(&Ks[pt][kr][kc]), g_ckb + (size_t)(n * SK + sb + kr) * CH + h * DH + kc);
        CP16(saddr(&Vs[pt][vr][vc]), g_cvt + (size_t)(nh * DH + vr) * SK + sb + vc);
        CP_COMMIT();
    }
    __syncthreads();   // Qs visible

    // hoist Q fragments (invariant over s-tiles)
    int r0 = wid * 16 + rg;
    uint32_t aq[2][4];
    #pragma unroll
    for (int ks = 0; ks < 2; ks++) {
        aq[ks][0] = *(uint32_t*)&Qs[r0    ][ks * 16 + qd * 2];
        aq[ks][1] = *(uint32_t*)&Qs[r0 + 8][ks * 16 + qd * 2];
        aq[ks][2] = *(uint32_t*)&Qs[r0    ][ks * 16 + qd * 2 + 8];
        aq[ks][3] = *(uint32_t*)&Qs[r0 + 8][ks * 16 + qd * 2 + 8];
    }

    float m0 = -1e30f, m1 = -1e30f, l0 = 0.f, l1 = 0.f;
    float o[4][4] = {};

    for (int kt = 0; kt < T; kt++) {
        CP_WAIT1();
        __syncthreads();
        int st = kt % 3;

        // S = Q @ K^T  (per warp: 16x64)
        float sc[8][4];
        #pragma unroll
        for (int j = 0; j < 8; j++)
            #pragma unroll
            for (int e = 0; e < 4; e++) sc[j][e] = 0.f;
        #pragma unroll
        for (int ks = 0; ks < 2; ks++) {
            #pragma unroll
            for (int j = 0; j < 8; j++) {
                uint32_t b0 = *(uint32_t*)&Ks[st][j * 8 + rg][ks * 16 + qd * 2];
                uint32_t b1 = *(uint32_t*)&Ks[st][j * 8 + rg][ks * 16 + qd * 2 + 8];
                mma_bf16(sc[j], aq[ks][0], aq[ks][1], aq[ks][2], aq[ks][3], b0, b1);
            }
        }

        // online softmax (scale folded into exp)
        float rm0 = -1e30f, rm1 = -1e30f;
        #pragma unroll
        for (int j = 0; j < 8; j++) {
            rm0 = fmaxf(rm0, fmaxf(sc[j][0], sc[j][1]));
            rm1 = fmaxf(rm1, fmaxf(sc[j][2], sc[j][3]));
        }
        rm0 = fmaxf(rm0, __shfl_xor_sync(0xffffffffu, rm0, 1));
        rm0 = fmaxf(rm0, __shfl_xor_sync(0xffffffffu, rm0, 2));
        rm1 = fmaxf(rm1, __shfl_xor_sync(0xffffffffu, rm1, 1));
        rm1 = fmaxf(rm1, __shfl_xor_sync(0xffffffffu, rm1, 2));
        float mn0 = fmaxf(m0, rm0), mn1 = fmaxf(m1, rm1);
        float corr0 = __expf((m0 - mn0) * scale);
        float corr1 = __expf((m1 - mn1) * scale);
        float s0 = 0.f, s1 = 0.f;
        #pragma unroll
        for (int j = 0; j < 8; j++) {
            sc[j][0] = __expf((sc[j][0] - mn0) * scale);
            sc[j][1] = __expf((sc[j][1] - mn0) * scale);
            sc[j][2] = __expf((sc[j][2] - mn1) * scale);
            sc[j][3] = __expf((sc[j][3] - mn1) * scale);
            s0 += sc[j][0] + sc[j][1];
            s1 += sc[j][2] + sc[j][3];
        }
        s0 += __shfl_xor_sync(0xffffffffu, s0, 1);
        s0 += __shfl_xor_sync(0xffffffffu, s0, 2);
        s1 += __shfl_xor_sync(0xffffffffu, s1, 1);
        s1 += __shfl_xor_sync(0xffffffffu, s1, 2);
        l0 = l0 * corr0 + s0;
        l1 = l1 * corr1 + s1;
        m0 = mn0; m1 = mn1;
        #pragma unroll
        for (int dj = 0; dj < 4; dj++) {
            o[dj][0] *= corr0; o[dj][1] *= corr0;
            o[dj][2] *= corr1; o[dj][3] *= corr1;
        }

        // O += P @ V
        #pragma unroll
        for (int t = 0; t < 4; t++) {
            uint32_t pa0 = pack_bf16(sc[2 * t    ][0], sc[2 * t    ][1]);
            uint32_t pa1 = pack_bf16(sc[2 * t    ][2], sc[2 * t    ][3]);
            uint32_t pa2 = pack_bf16(sc[2 * t + 1][0], sc[2 * t + 1][1]);
            uint32_t pa3 = pack_bf16(sc[2 * t + 1][2], sc[2 * t + 1][3]);
            #pragma unroll
            for (int dj = 0; dj < 4; dj++) {
                uint32_t b0 = *(uint32_t*)&Vs[st][dj * 8 + rg][t * 16 + qd * 2];
                uint32_t b1 = *(uint32_t*)&Vs[st][dj * 8 + rg][t * 16 + qd * 2 + 8];
                mma_bf16(o[dj], pa0, pa1, pa2, pa3, b0, b1);
            }
        }

        // prefetch tile kt+2
        if (kt + 2 < T) {
            int st2 = (kt + 2) % 3, sb = (kt + 2) * 64;
            CP16(saddr(&Ks[st2][kr][kc]), g_ckb + (size_t)(n * SK + sb + kr) * CH + h * DH + kc);
            CP16(saddr(&Vs[st2][vr][vc]), g_cvt + (size_t)(nh * DH + vr) * SK + sb + vc);
        }
        CP_COMMIT();
    }

    float inv0 = 1.f / l0, inv1 = 1.f / l1;
    #pragma unroll
    for (int dj = 0; dj < 4; dj++) {
        size_t b0 = (size_t)(n * LQ + qb + r0    ) * CH + h * DH + dj * 8 + qd * 2;
        size_t b1 = (size_t)(n * LQ + qb + r0 + 8) * CH + h * DH + dj * 8 + qd * 2;
        *(__nv_bfloat162*)&g_cob[b0] = __float22bfloat162_rn(make_float2(o[dj][0] * inv0, o[dj][1] * inv0));
        *(__nv_bfloat162*)&g_cob[b1] = __float22bfloat162_rn(make_float2(o[dj][2] * inv1, o[dj][3] * inv1));
    }
}

// ---------------- depthwise conv3 (along L) + bias + exact gelu (bf16 in/out) ----------------
__global__ void conv_gelu(const float* __restrict__ dwk, const float* __restrict__ dwb)
{
    int i = blockIdx.x * blockDim.x + threadIdx.x;
    int c = i & (HID - 1);
    int l = (i >> 10) & (LQ - 1);
    float k0 = dwk[c * 9 + 1];
    float k1 = dwk[c * 9 + 4];
    float k2 = dwk[c * 9 + 7];
    float v = __bfloat162float(g_hb[i]) * k1;
    if (l > 0)      v += __bfloat162float(g_hb[i - HID]) * k0;
    if (l < LQ - 1) v += __bfloat162float(g_hb[i + HID]) * k2;
    v += dwb[c];
    float out = 0.5f * v * (1.f + erff(v * 0.70710678118654752f));
    g_h2b[i] = __float2bfloat16(out);
}

// ---------------- host ----------------
extern "C" void kernel_launch(void* const* d_in, const int* in_sizes, int n_in,
                              void* d_out, int out_size)
{
    const float* tgt      = (const float*)d_in[0];
    const float* memory   = (const float*)d_in[1];
    const float* tgt_pos  = (const float*)d_in[2];
    const float* pos_emb  = (const float*)d_in[3];
    const float* ln1_g = (const float*)d_in[4],  *ln1_b = (const float*)d_in[5];
    const float* ln2_g = (const float*)d_in[6],  *ln2_b = (const float*)d_in[7];
    const float* ln3_g = (const float*)d_in[8],  *ln3_b = (const float*)d_in[9];
    const float* wq = (const float*)d_in[10], *bq = (const float*)d_in[11];
    const float* wk = (const float*)d_in[12], *bk = (const float*)d_in[13];
    const float* wv = (const float*)d_in[14], *bv = (const float*)d_in[15];
    const float* w_merge = (const float*)d_in[16];
    const float* cwq = (const float*)d_in[17], *cbq = (const float*)d_in[18];
    const float* cwk = (const float*)d_in[19], *cbk = (const float*)d_in[20];
    const float* cwv = (const float*)d_in[21], *cbv = (const float*)d_in[22];
    const float* cwo = (const float*)d_in[23], *cbo = (const float*)d_in[24];
    const float* mw1 = (const float*)d_in[25], *mb1 = (const float*)d_in[26];
    const float* dwk = (const float*)d_in[27], *dwb = (const float*)d_in[28];
    const float* mw2 = (const float*)d_in[29], *mb2 = (const float*)d_in[30];
    float* out = (float*)d_out;

    float *p_q, *p_k, *p_v, *p_t1, *p_t2;
    __nv_bfloat16 *p_xb1, *p_xb2, *p_laob, *p_memb, *p_cqb, *p_ckb, *p_cvb, *p_cob, *p_hb, *p_h2b, *p_wts;
    cudaGetSymbolAddress((void**)&p_q,    g_q);
    cudaGetSymbolAddress((void**)&p_k,    g_k);
    cudaGetSymbolAddress((void**)&p_v,    g_v);
    cudaGetSymbolAddress((void**)&p_t1,   g_t1);
    cudaGetSymbolAddress((void**)&p_t2,   g_t2);
    cudaGetSymbolAddress((void**)&p_xb1,  g_xb1);
    cudaGetSymbolAddress((void**)&p_xb2,  g_xb2);
    cudaGetSymbolAddress((void**)&p_laob, g_laob);
    cudaGetSymbolAddress((void**)&p_memb, g_memb);
    cudaGetSymbolAddress((void**)&p_cqb,  g_cqb);
    cudaGetSymbolAddress((void**)&p_ckb,  g_ckb);
    cudaGetSymbolAddress((void**)&p_cvb,  g_cvb);
    cudaGetSymbolAddress((void**)&p_cob,  g_cob);
    cudaGetSymbolAddress((void**)&p_hb,   g_hb);
    cudaGetSymbolAddress((void**)&p_h2b,  g_h2b);
    cudaGetSymbolAddress((void**)&p_wts,  g_wts);

    // ---- fused weight transpose (1 launch) ----
    WSrc ws;
    ws.p[0] = wq;  ws.p[1] = wk;  ws.p[2] = wv;  ws.p[3] = w_merge;
    ws.p[4] = cwq; ws.p[5] = cwk; ws.p[6] = cwv; ws.p[7] = cwo;
    ws.p[8] = mw1; ws.p[9] = mw2;
    wtrans_all<<<1024, dim3(32, 8)>>>(ws, p_wts);

    dim3 gq(CH / 64, NLROWS / 128);        // (4,64)
    dim3 gdual(2 * CH / 64, NLROWS / 128); // (8,64)
    dim3 gmemd(2 * CH / 64, NSROWS / 128); // (8,128)
    dim3 gm1(HID / 64, NLROWS / 128);      // (16,64)

    // ---- self attention (linear attention) ----
    ln_kernel<<<NLROWS, 256>>>(tgt, ln1_g, ln1_b, tgt_pos, p_xb1, p_xb2);
    gemm_bf16<1, false, true><<<gdual, 256>>>(p_xb2, p_wts + WT_WQ, bq, bk, nullptr,
                                              p_q, p_k, NLROWS, CH, CH);
    gemm_bf16<0, false, false><<<gq, 256>>>(p_xb1, p_wts + WT_WV, bv, nullptr, nullptr,
                                            p_v, nullptr, NLROWS, CH, CH);
    kv_accum<<<dim3(NB * NH, 8), 1024>>>();
    kv_reduce<<<NB * NH, 1024>>>();
    lin_out<<<NLROWS, 256>>>();
    gemm_bf16<2, false, false><<<gq, 256>>>(p_laob, p_wts + WT_WM, nullptr, nullptr, tgt,
                                            p_t1, nullptr, NLROWS, CH, CH);

    // ---- cross attention ----
    ln_kernel<<<NLROWS, 256>>>(p_t1, ln2_g, ln2_b, nullptr, p_xb1, nullptr);
    mem_add<<<NSROWS * CH / 4 / 256, 256>>>(memory, pos_emb);
    gemm_bf16<0, true, false><<<gq, 256>>>(p_xb1, p_wts + WT_CWQ, cbq, nullptr, nullptr,
                                           p_cqb, nullptr, NLROWS, CH, CH);
    gemm_bf16<0, true, true><<<gmemd, 256>>>(p_memb, p_wts + WT_CWK, cbk, cbv, nullptr,
                                             p_ckb, p_cvb, NSROWS, CH, CH);
    vtrans<<<dim3(SK / 32, NB * NH), dim3(32, 8)>>>();
    flash_attn_mma<<<dim3(LQ / 128, NH, NB), 256>>>();
    gemm_bf16<2, false, false><<<gq, 256>>>(p_cob, p_wts + WT_CWO, cbo, nullptr, p_t1,
                                            p_t2, nullptr, NLROWS, CH, CH);

    // ---- MLP ----
    ln_kernel<<<NLROWS, 256>>>(p_t2, ln3_g, ln3_b, nullptr, p_xb1, nullptr);
    gemm_bf16<0, true, false><<<gm1, 256>>>(p_xb1, p_wts + WT_MW1, mb1, nullptr, nullptr,
                                            p_hb, nullptr, NLROWS, CH, HID);
    conv_gelu<<<NLROWS * HID / 256, 256>>>(dwk, dwb);
    gemm_bf16<2, false, false><<<gq, 256>>>(p_h2b, p_wts + WT_MW2, mb2, nullptr, p_t2,
                                            out, nullptr, NLROWS, HID, CH);
}

// round 5
// speedup vs baseline: 4.4663x; 1.0443x over previous
#include <cuda_runtime.h>
#include <cuda_bf16.h>
#include <math.h>
#include <stdint.h>

#define NB 4
#define LQ 2048
#define SK 4096
#define CH 256
#define NH 8
#define DH 32
#define HID 1024
#define NLROWS (NB*LQ)      // 8192
#define NSROWS (NB*SK)      // 16384

// ---------------- scratch (device globals; no runtime alloc) ----------------
__device__ float g_q   [NLROWS*CH];
__device__ float g_k   [NLROWS*CH];
__device__ float g_v   [NLROWS*CH];
__device__ float g_t1  [NLROWS*CH];
__device__ float g_t2  [NLROWS*CH];
__device__ float g_kv  [NB*NH*DH*DH];
__device__ float g_ksum[NB*NH*DH];
__device__ float g_kvp [NB*NH*8*DH*DH];
__device__ float g_ksp [NB*NH*8*DH];

__device__ __nv_bfloat16 g_xb1 [NLROWS*CH];
__device__ __nv_bfloat16 g_xb2 [NLROWS*CH];
__device__ __nv_bfloat16 g_laob[NLROWS*CH];
__device__ __nv_bfloat16 g_memb[NSROWS*CH];
__device__ __nv_bfloat16 g_cqb [NLROWS*CH];
__device__ __nv_bfloat16 g_ckb [NSROWS*CH];
__device__ __nv_bfloat16 g_cvb [NSROWS*CH];
__device__ __nv_bfloat16 g_cvt [NB*NH*DH*SK];
__device__ __nv_bfloat16 g_cob [NLROWS*CH];
__device__ __nv_bfloat16 g_hb  [NLROWS*HID];
__device__ __nv_bfloat16 g_h2b [NLROWS*HID];
__device__ __nv_bfloat16 g_wts [8*CH*CH + CH*HID + HID*CH];

#define WT_WQ   0
#define WT_WK   (1*CH*CH)
#define WT_WV   (2*CH*CH)
#define WT_WM   (3*CH*CH)
#define WT_CWQ  (4*CH*CH)
#define WT_CWK  (5*CH*CH)
#define WT_CWV  (6*CH*CH)
#define WT_CWO  (7*CH*CH)
#define WT_MW1  (8*CH*CH)
#define WT_MW2  (8*CH*CH + CH*HID)

// ---------------- helpers ----------------
__device__ __forceinline__ void mma_bf16(float* c, uint32_t a0, uint32_t a1, uint32_t a2, uint32_t a3,
                                         uint32_t b0, uint32_t b1)
{
    asm volatile("mma.sync.aligned.m16n8k16.row.col.f32.bf16.bf16.f32 "
                 "{%0,%1,%2,%3}, {%4,%5,%6,%7}, {%8,%9}, {%0,%1,%2,%3};"
                 : "+f"(c[0]), "+f"(c[1]), "+f"(c[2]), "+f"(c[3])
                 : "r"(a0), "r"(a1), "r"(a2), "r"(a3), "r"(b0), "r"(b1));
}

__device__ __forceinline__ void ldsm4(uint32_t& r0, uint32_t& r1, uint32_t& r2, uint32_t& r3, uint32_t a)
{
    asm volatile("ldmatrix.sync.aligned.m8n8.x4.shared.b16 {%0,%1,%2,%3}, [%4];"
                 : "=r"(r0), "=r"(r1), "=r"(r2), "=r"(r3) : "r"(a));
}

__device__ __forceinline__ uint32_t pack_bf16(float lo, float hi)
{
    __nv_bfloat162 t = __float22bfloat162_rn(make_float2(lo, hi));
    return *(uint32_t*)&t;
}

__device__ __forceinline__ uint32_t saddr(const void* p)
{
    return (uint32_t)__cvta_generic_to_shared(p);
}

#define CP16(dst, src) asm volatile("cp.async.cg.shared.global [%0], [%1], 16;" :: "r"(dst), "l"(src))
#define CP_COMMIT()    asm volatile("cp.async.commit_group;")
#define CP_WAIT1()     asm volatile("cp.async.wait_group 1;")

// ---------------- fused weight transpose: all 10 weights in one launch ----------------
struct WSrc { const float* p[10]; };

__global__ void wtrans_all(WSrc ws, __nv_bfloat16* __restrict__ dst)
{
    __shared__ float t[32][33];
    int bid = blockIdx.x;
    int w, kt, nt;
    if (bid < 512)       { w = bid >> 6;  int r = bid & 63;   kt = r >> 3; nt = r & 7;  }
    else if (bid < 768)  { w = 8;         int r = bid - 512;  kt = r >> 5; nt = r & 31; }
    else                 { w = 9;         int r = bid - 768;  kt = r >> 3; nt = r & 7;  }
    int Kd = (w == 9) ? 1024 : 256;
    int Nd = (w == 8) ? 1024 : 256;
    size_t doff = (w < 8) ? (size_t)w * (CH*CH) : (w == 8 ? (size_t)8*CH*CH : (size_t)8*CH*CH + CH*HID);
    const float* W = ws.p[w];
    __nv_bfloat16* Wt = dst + doff;
    int n0 = nt * 32, k0 = kt * 32;
    int tx = threadIdx.x, ty = threadIdx.y;   // (32,8)
    #pragma unroll
    for (int i = 0; i < 4; i++)
        t[ty + i * 8][tx] = W[(size_t)(k0 + ty + i * 8) * Nd + n0 + tx];
    __syncthreads();
    #pragma unroll
    for (int i = 0; i < 4; i++)
        Wt[(size_t)(n0 + ty + i * 8) * Kd + k0 + tx] = __float2bfloat16(t[tx][ty + i * 8]);
}

// ---------------- LayerNorm: bf16 outputs (y, optional y2=y+addp) ----------------
__global__ void ln_kernel(const float* __restrict__ x, const float* __restrict__ g,
                          const float* __restrict__ b, const float* __restrict__ addp,
                          __nv_bfloat16* __restrict__ y, __nv_bfloat16* __restrict__ y2)
{
    int row = blockIdx.x, tid = threadIdx.x;
    size_t base = (size_t)row * CH;
    float v = x[base + tid];
    float s1 = v, s2 = v * v;
    #pragma unroll
    for (int off = 16; off > 0; off >>= 1) {
        s1 += __shfl_xor_sync(0xffffffffu, s1, off);
        s2 += __shfl_xor_sync(0xffffffffu, s2, off);
    }
    __shared__ float r1[8], r2[8];
    int warp = tid >> 5, lane = tid & 31;
    if (lane == 0) { r1[warp] = s1; r2[warp] = s2; }
    __syncthreads();
    float t1 = 0.f, t2 = 0.f;
    #pragma unroll
    for (int w = 0; w < 8; w++) { t1 += r1[w]; t2 += r2[w]; }
    float mean = t1 * (1.f / CH);
    float var  = t2 * (1.f / CH) - mean * mean;
    float inv  = rsqrtf(var + 1e-5f);
    float out  = (v - mean) * inv * g[tid] + b[tid];
    y[base + tid] = __float2bfloat16(out);
    if (y2) y2[base + tid] = __float2bfloat16(out + addp[base + tid]);
}

// ---------------- bf16 tensor-core GEMM, 3-stage cp.async, ldmatrix frags ----------------
// BM in {64,128}; blockDim = 2*BM. Warp tile 32x32; BN=64.
// EPI 0: +bias ; EPI 1: elu(z)+1 ; EPI 2: +bias +res.  OUTBF: write bf16.
template<int EPI, bool OUTBF, bool DUAL, int BM>
__global__ void gemm_bf16(const __nv_bfloat16* __restrict__ X, const __nv_bfloat16* __restrict__ Wt,
                          const float* __restrict__ bias, const float* __restrict__ bias2,
                          const float* __restrict__ res,
                          void* __restrict__ Yv, void* __restrict__ Yv2,
                          int M, int K, int NOUT)
{
    __shared__ __nv_bfloat16 As[3][BM][40];
    __shared__ __nv_bfloat16 Bs[3][64][40];
    int tid = threadIdx.x;
    int lane = tid & 31, wid = tid >> 5;
    int qd = lane & 3, rg = lane >> 2;
    int wm = wid >> 1, wn = wid & 1;
    int row0 = blockIdx.y * BM, col0 = blockIdx.x * 64;

    float acc[2][4][4];
    #pragma unroll
    for (int mi = 0; mi < 2; mi++)
        #pragma unroll
        for (int nj = 0; nj < 4; nj++)
            #pragma unroll
            for (int e = 0; e < 4; e++) acc[mi][nj][e] = 0.f;

    int ar = tid >> 2, ac = (tid & 3) * 8;

    // ldmatrix lane offsets (elements)
    int laneA = ((lane & 7) + ((lane >> 3) & 1) * 8) * 40 + (lane >> 4) * 8;
    int laneB = ((lane & 7) + (lane >> 4) * 8) * 40 + ((lane >> 3) & 1) * 8;

    const int T = K / 32;
    #pragma unroll
    for (int pt = 0; pt < 2; pt++) {
        if (pt < T) {
            int k0 = pt * 32;
            CP16(saddr(&As[pt][ar][ac]),          X  + (size_t)(row0 + ar) * K + k0 + ac);
            CP16(saddr(&As[pt][ar + BM/2][ac]),   X  + (size_t)(row0 + ar + BM/2) * K + k0 + ac);
            CP16(saddr(&Bs[pt][ar][ac]),          Wt + (size_t)(col0 + ar) * K + k0 + ac);
            if (BM == 64)
                CP16(saddr(&Bs[pt][ar + 32][ac]), Wt + (size_t)(col0 + ar + 32) * K + k0 + ac);
        }
        CP_COMMIT();
    }

    for (int kt = 0; kt < T; kt++) {
        CP_WAIT1();
        __syncthreads();
        int st = kt % 3;
        uint32_t abase = saddr(&As[st][0][0]) + 2 * (wm * 32 * 40 + laneA);
        uint32_t bbase = saddr(&Bs[st][0][0]) + 2 * (wn * 32 * 40 + laneB);
        #pragma unroll
        for (int ks = 0; ks < 2; ks++) {
            uint32_t a[2][4], b[2][4];
            ldsm4(a[0][0], a[0][1], a[0][2], a[0][3], abase + 2 * (ks * 16));
            ldsm4(a[1][0], a[1][1], a[1][2], a[1][3], abase + 2 * (16 * 40 + ks * 16));
            ldsm4(b[0][0], b[0][1], b[0][2], b[0][3], bbase + 2 * (ks * 16));
            ldsm4(b[1][0], b[1][1], b[1][2], b[1][3], bbase + 2 * (16 * 40 + ks * 16));
            #pragma unroll
            for (int mi = 0; mi < 2; mi++) {
                mma_bf16(acc[mi][0], a[mi][0], a[mi][1], a[mi][2], a[mi][3], b[0][0], b[0][1]);
                mma_bf16(acc[mi][1], a[mi][0], a[mi][1], a[mi][2], a[mi][3], b[0][2], b[0][3]);
                mma_bf16(acc[mi][2], a[mi][0], a[mi][1], a[mi][2], a[mi][3], b[1][0], b[1][1]);
                mma_bf16(acc[mi][3], a[mi][0], a[mi][1], a[mi][2], a[mi][3], b[1][2], b[1][3]);
            }
        }
        if (kt + 2 < T) {
            int st2 = (kt + 2) % 3, k0 = (kt + 2) * 32;
            CP16(saddr(&As[st2][ar][ac]),          X  + (size_t)(row0 + ar) * K + k0 + ac);
            CP16(saddr(&As[st2][ar + BM/2][ac]),   X  + (size_t)(row0 + ar + BM/2) * K + k0 + ac);
            CP16(saddr(&Bs[st2][ar][ac]),          Wt + (size_t)(col0 + ar) * K + k0 + ac);
            if (BM == 64)
                CP16(saddr(&Bs[st2][ar + 32][ac]), Wt + (size_t)(col0 + ar + 32) * K + k0 + ac);
        }
        CP_COMMIT();
    }

    #pragma unroll
    for (int mi = 0; mi < 2; mi++) {
        #pragma unroll
        for (int nj = 0; nj < 4; nj++) {
            int r = row0 + wm * 32 + mi * 16 + rg;
            int c = col0 + wn * 32 + nj * 8 + qd * 2;
            void* Yp = Yv;
            const float* bp = bias;
            int cc = c;
            if (DUAL && c >= NOUT) { Yp = Yv2; bp = bias2; cc = c - NOUT; }
            float b0v = bp ? bp[cc] : 0.f;
            float b1v = bp ? bp[cc + 1] : 0.f;
            #pragma unroll
            for (int half = 0; half < 2; half++) {
                int rr = r + half * 8;
                float z0 = acc[mi][nj][half * 2 + 0] + b0v;
                float z1 = acc[mi][nj][half * 2 + 1] + b1v;
                if (EPI == 1) {
                    z0 = (z0 > 0.f) ? (z0 + 1.f) : __expf(z0);
                    z1 = (z1 > 0.f) ? (z1 + 1.f) : __expf(z1);
                } else if (EPI == 2) {
                    const float2 rv = *(const float2*)&res[(size_t)rr * NOUT + cc];
                    z0 += rv.x; z1 += rv.y;
                }
                size_t off = (size_t)rr * NOUT + cc;
                if (OUTBF) {
                    *(__nv_bfloat162*)((__nv_bfloat16*)Yp + off) =
                        __float22bfloat162_rn(make_float2(z0, z1));
                } else {
                    *(float2*)((float*)Yp + off) = make_float2(z0, z1);
                }
            }
        }
    }
}

// ---------------- linear-attn KV/Ksum partials ----------------
__global__ void kv_accum()
{
    int nh = blockIdx.x, part = blockIdx.y;
    int n = nh >> 3, h = nh & 7;
    int tid = threadIdx.x;          // 1024
    int d = tid >> 5, vv = tid & 31;
    __shared__ float sk[64][32], sv[64][32];
    float acc = 0.f, ks = 0.f;
    int base = part * 256;
    for (int c0 = base; c0 < base + 256; c0 += 64) {
        __syncthreads();
        #pragma unroll
        for (int it = 0; it < 2; it++) {
            int idx = tid + it * 1024;
            int s = idx >> 5, dd = idx & 31;
            size_t gbase = (size_t)(n * LQ + c0 + s) * CH + h * DH + dd;
            sk[s][dd] = g_k[gbase];
            sv[s][dd] = g_v[gbase];
        }
        __syncthreads();
        #pragma unroll
        for (int s = 0; s < 64; s++) {
            float kd = sk[s][d];
            acc += kd * sv[s][vv];
            ks  += kd;
        }
    }
    g_kvp[(size_t)((nh << 3) + part) * (DH*DH) + d * DH + vv] = acc;
    if (vv == 0) g_ksp[((nh << 3) + part) * DH + d] = ks;
}

__global__ void kv_reduce()
{
    int nh = blockIdx.x, i = threadIdx.x;
    float s = 0.f;
    #pragma unroll
    for (int p = 0; p < 8; p++) s += g_kvp[(size_t)((nh << 3) + p) * (DH*DH) + i];
    g_kv[(size_t)nh * (DH*DH) + i] = s;
    if (i < DH) {
        float ks = 0.f;
        #pragma unroll
        for (int p = 0; p < 8; p++) ks += g_ksp[((nh << 3) + p) * DH + i];
        g_ksum[nh * DH + i] = ks;
    }
}

// ---------------- linear-attn output (bf16 out) ----------------
__global__ void lin_out()
{
    int row = blockIdx.x;
    int n = row >> 11;
    int tid = threadIdx.x;
    int h = tid >> 5, lane = tid & 31;
    __shared__ float qsh[CH];
    qsh[tid] = g_q[(size_t)row * CH + tid];
    __syncthreads();
    int nh = n * NH + h;
    float z = qsh[h * DH + lane] * g_ksum[nh * DH + lane];
    #pragma unroll
    for (int off = 16; off > 0; off >>= 1) z += __shfl_xor_sync(0xffffffffu, z, off);
    float zinv = 1.f / (z + 1e-6f);
    const float* kvp = g_kv + (size_t)nh * (DH*DH);
    float acc = 0.f;
    #pragma unroll
    for (int dd = 0; dd < DH; dd++) acc += qsh[h * DH + dd] * kvp[dd * DH + lane];
    g_laob[(size_t)row * CH + tid] = __float2bfloat16(acc * zinv);
}

// ---------------- mem = bf16(memory + pos_embed) ----------------
__global__ void mem_add(const float* __restrict__ memory, const float* __restrict__ pos)
{
    int i4 = blockIdx.x * blockDim.x + threadIdx.x;
    const int PER_N = SK * CH / 4;
    int p4 = i4 % PER_N;
    float4 a = ((const float4*)memory)[i4];
    float4 b = ((const float4*)pos)[p4];
    uint32_t lo = pack_bf16(a.x + b.x, a.y + b.y);
    uint32_t hi = pack_bf16(a.z + b.z, a.w + b.w);
    ((uint2*)g_memb)[i4] = make_uint2(lo, hi);
}

// ---------------- V transpose per (n,h): [s][d] -> [d][s] ----------------
__global__ void vtrans()
{
    __shared__ __nv_bfloat16 t[32][33];
    int s0 = blockIdx.x * 32;
    int nh = blockIdx.y;
    int n = nh >> 3, h = nh & 7;
    int tx = threadIdx.x, ty = threadIdx.y;   // (32,8)
    #pragma unroll
    for (int i = 0; i < 4; i++)
        t[ty + i * 8][tx] = g_cvb[(size_t)(n * SK + s0 + ty + i * 8) * CH + h * DH + tx];
    __syncthreads();
    #pragma unroll
    for (int i = 0; i < 4; i++)
        g_cvt[(size_t)(nh * DH + ty + i * 8) * SK + s0 + tx] = t[tx][ty + i * 8];
}

// ---------------- flash attention: 128q x 64s tiles, 8 warps, 3-stage, ldmatrix ----------------
__global__ void flash_attn_mma()
{
    __shared__ __nv_bfloat16 Qs[128][36];
    __shared__ __nv_bfloat16 Ks[3][64][40];
    __shared__ __nv_bfloat16 Vs[3][32][72];
    int tid = threadIdx.x;               // 256
    int lane = tid & 31, wid = tid >> 5;
    int qd = lane & 3, rg = lane >> 2;
    int qb = blockIdx.x * 128, h = blockIdx.y, n = blockIdx.z;
    int nh = n * NH + h;
    const float scale = 0.17677669529663687f;   // 32^-0.5

    // load Q tile
    #pragma unroll
    for (int i = 0; i < 8; i++) {
        int idx = tid + i * 256;
        int r = idx >> 4, dp = idx & 15;
        uint32_t v = *(const uint32_t*)&g_cqb[(size_t)(n * LQ + qb + r) * CH + h * DH + dp * 2];
        *(uint32_t*)&Qs[r][dp * 2] = v;
    }

    // prologue: K/V tiles 0, 1
    int kr = tid >> 2, kc = (tid & 3) * 8;
    int vr = tid >> 3, vc = (tid & 7) * 8;
    const int T = SK / 64;
    #pragma unroll
    for (int pt = 0; pt < 2; pt++) {
        int sb = pt * 64;
        CP16(saddr(&Ks[pt][kr][kc]), g_ckb + (size_t)(n * SK + sb + kr) * CH + h * DH + kc);
        CP16(saddr(&Vs[pt][vr][vc]), g_cvt + (size_t)(nh * DH + vr) * SK + sb + vc);
        CP_COMMIT();
    }
    __syncthreads();   // Qs visible

    // hoist Q fragments
    int r0 = wid * 16 + rg;
    uint32_t aq[2][4];
    #pragma unroll
    for (int ks = 0; ks < 2; ks++) {
        aq[ks][0] = *(uint32_t*)&Qs[r0    ][ks * 16 + qd * 2];
        aq[ks][1] = *(uint32_t*)&Qs[r0 + 8][ks * 16 + qd * 2];
        aq[ks][2] = *(uint32_t*)&Qs[r0    ][ks * 16 + qd * 2 + 8];
        aq[ks][3] = *(uint32_t*)&Qs[r0 + 8][ks * 16 + qd * 2 + 8];
    }

    // ldmatrix lane offsets
    int laneK = ((lane & 7) + (lane >> 4) * 8) * 40 + ((lane >> 3) & 1) * 8;
    int laneV = ((lane & 7) + (lane >> 4) * 8) * 72 + ((lane >> 3) & 1) * 8;

    float m0 = -1e30f, m1 = -1e30f, l0 = 0.f, l1 = 0.f;
    float o[4][4] = {};

    for (int kt = 0; kt < T; kt++) {
        CP_WAIT1();
        __syncthreads();
        int st = kt % 3;

        // S = Q @ K^T
        float sc[8][4];
        #pragma unroll
        for (int j = 0; j < 8; j++)
            #pragma unroll
            for (int e = 0; e < 4; e++) sc[j][e] = 0.f;
        uint32_t kb = saddr(&Ks[st][0][0]) + 2 * laneK;
        #pragma unroll
        for (int ks = 0; ks < 2; ks++) {
            #pragma unroll
            for (int jj = 0; jj < 4; jj++) {
                uint32_t b0, b1, b2, b3;
                ldsm4(b0, b1, b2, b3, kb + 2 * (jj * 16 * 40 + ks * 16));
                mma_bf16(sc[2 * jj    ], aq[ks][0], aq[ks][1], aq[ks][2], aq[ks][3], b0, b1);
                mma_bf16(sc[2 * jj + 1], aq[ks][0], aq[ks][1], aq[ks][2], aq[ks][3], b2, b3);
            }
        }

        // online softmax
        float rm0 = -1e30f, rm1 = -1e30f;
        #pragma unroll
        for (int j = 0; j < 8; j++) {
            rm0 = fmaxf(rm0, fmaxf(sc[j][0], sc[j][1]));
            rm1 = fmaxf(rm1, fmaxf(sc[j][2], sc[j][3]));
        }
        rm0 = fmaxf(rm0, __shfl_xor_sync(0xffffffffu, rm0, 1));
        rm0 = fmaxf(rm0, __shfl_xor_sync(0xffffffffu, rm0, 2));
        rm1 = fmaxf(rm1, __shfl_xor_sync(0xffffffffu, rm1, 1));
        rm1 = fmaxf(rm1, __shfl_xor_sync(0xffffffffu, rm1, 2));
        float mn0 = fmaxf(m0, rm0), mn1 = fmaxf(m1, rm1);
        float corr0 = __expf((m0 - mn0) * scale);
        float corr1 = __expf((m1 - mn1) * scale);
        float s0 = 0.f, s1 = 0.f;
        #pragma unroll
        for (int j = 0; j < 8; j++) {
            sc[j][0] = __expf((sc[j][0] - mn0) * scale);
            sc[j][1] = __expf((sc[j][1] - mn0) * scale);
            sc[j][2] = __expf((sc[j][2] - mn1) * scale);
            sc[j][3] = __expf((sc[j][3] - mn1) * scale);
            s0 += sc[j][0] + sc[j][1];
            s1 += sc[j][2] + sc[j][3];
        }
        s0 += __shfl_xor_sync(0xffffffffu, s0, 1);
        s0 += __shfl_xor_sync(0xffffffffu, s0, 2);
        s1 += __shfl_xor_sync(0xffffffffu, s1, 1);
        s1 += __shfl_xor_sync(0xffffffffu, s1, 2);
        l0 = l0 * corr0 + s0;
        l1 = l1 * corr1 + s1;
        m0 = mn0; m1 = mn1;
        #pragma unroll
        for (int dj = 0; dj < 4; dj++) {
            o[dj][0] *= corr0; o[dj][1] *= corr0;
            o[dj][2] *= corr1; o[dj][3] *= corr1;
        }

        // O += P @ V
        uint32_t vb = saddr(&Vs[st][0][0]) + 2 * laneV;
        #pragma unroll
        for (int t = 0; t < 4; t++) {
            uint32_t pa0 = pack_bf16(sc[2 * t    ][0], sc[2 * t    ][1]);
            uint32_t pa1 = pack_bf16(sc[2 * t    ][2], sc[2 * t    ][3]);
            uint32_t pa2 = pack_bf16(sc[2 * t + 1][0], sc[2 * t + 1][1]);
            uint32_t pa3 = pack_bf16(sc[2 * t + 1][2], sc[2 * t + 1][3]);
            #pragma unroll
            for (int dd = 0; dd < 2; dd++) {
                uint32_t v0, v1, v2, v3;
                ldsm4(v0, v1, v2, v3, vb + 2 * (dd * 16 * 72 + t * 16));
                mma_bf16(o[2 * dd    ], pa0, pa1, pa2, pa3, v0, v1);
                mma_bf16(o[2 * dd + 1], pa0, pa1, pa2, pa3, v2, v3);
            }
        }

        // prefetch tile kt+2
        if (kt + 2 < T) {
            int st2 = (kt + 2) % 3, sb = (kt + 2) * 64;
            CP16(saddr(&Ks[st2][kr][kc]), g_ckb + (size_t)(n * SK + sb + kr) * CH + h * DH + kc);
            CP16(saddr(&Vs[st2][vr][vc]), g_cvt + (size_t)(nh * DH + vr) * SK + sb + vc);
        }
        CP_COMMIT();
    }

    float inv0 = 1.f / l0, inv1 = 1.f / l1;
    #pragma unroll
    for (int dj = 0; dj < 4; dj++) {
        size_t b0 = (size_t)(n * LQ + qb + r0    ) * CH + h * DH + dj * 8 + qd * 2;
        size_t b1 = (size_t)(n * LQ + qb + r0 + 8) * CH + h * DH + dj * 8 + qd * 2;
        *(__nv_bfloat162*)&g_cob[b0] = __float22bfloat162_rn(make_float2(o[dj][0] * inv0, o[dj][1] * inv0));
        *(__nv_bfloat162*)&g_cob[b1] = __float22bfloat162_rn(make_float2(o[dj][2] * inv1, o[dj][3] * inv1));
    }
}

// ---------------- depthwise conv3 (along L) + bias + exact gelu (bf16 in/out) ----------------
__global__ void conv_gelu(const float* __restrict__ dwk, const float* __restrict__ dwb)
{
    int i = blockIdx.x * blockDim.x + threadIdx.x;
    int c = i & (HID - 1);
    int l = (i >> 10) & (LQ - 1);
    float k0 = dwk[c * 9 + 1];
    float k1 = dwk[c * 9 + 4];
    float k2 = dwk[c * 9 + 7];
    float v = __bfloat162float(g_hb[i]) * k1;
    if (l > 0)      v += __bfloat162float(g_hb[i - HID]) * k0;
    if (l < LQ - 1) v += __bfloat162float(g_hb[i + HID]) * k2;
    v += dwb[c];
    float out = 0.5f * v * (1.f + erff(v * 0.70710678118654752f));
    g_h2b[i] = __float2bfloat16(out);
}

// ---------------- host ----------------
extern "C" void kernel_launch(void* const* d_in, const int* in_sizes, int n_in,
                              void* d_out, int out_size)
{
    const float* tgt      = (const float*)d_in[0];
    const float* memory   = (const float*)d_in[1];
    const float* tgt_pos  = (const float*)d_in[2];
    const float* pos_emb  = (const float*)d_in[3];
    const float* ln1_g = (const float*)d_in[4],  *ln1_b = (const float*)d_in[5];
    const float* ln2_g = (const float*)d_in[6],  *ln2_b = (const float*)d_in[7];
    const float* ln3_g = (const float*)d_in[8],  *ln3_b = (const float*)d_in[9];
    const float* wq = (const float*)d_in[10], *bq = (const float*)d_in[11];
    const float* wk = (const float*)d_in[12], *bk = (const float*)d_in[13];
    const float* wv = (const float*)d_in[14], *bv = (const float*)d_in[15];
    const float* w_merge = (const float*)d_in[16];
    const float* cwq = (const float*)d_in[17], *cbq = (const float*)d_in[18];
    const float* cwk = (const float*)d_in[19], *cbk = (const float*)d_in[20];
    const float* cwv = (const float*)d_in[21], *cbv = (const float*)d_in[22];
    const float* cwo = (const float*)d_in[23], *cbo = (const float*)d_in[24];
    const float* mw1 = (const float*)d_in[25], *mb1 = (const float*)d_in[26];
    const float* dwk = (const float*)d_in[27], *dwb = (const float*)d_in[28];
    const float* mw2 = (const float*)d_in[29], *mb2 = (const float*)d_in[30];
    float* out = (float*)d_out;

    float *p_q, *p_k, *p_v, *p_t1, *p_t2;
    __nv_bfloat16 *p_xb1, *p_xb2, *p_laob, *p_memb, *p_cqb, *p_ckb, *p_cvb, *p_cob, *p_hb, *p_h2b, *p_wts;
    cudaGetSymbolAddress((void**)&p_q,    g_q);
    cudaGetSymbolAddress((void**)&p_k,    g_k);
    cudaGetSymbolAddress((void**)&p_v,    g_v);
    cudaGetSymbolAddress((void**)&p_t1,   g_t1);
    cudaGetSymbolAddress((void**)&p_t2,   g_t2);
    cudaGetSymbolAddress((void**)&p_xb1,  g_xb1);
    cudaGetSymbolAddress((void**)&p_xb2,  g_xb2);
    cudaGetSymbolAddress((void**)&p_laob, g_laob);
    cudaGetSymbolAddress((void**)&p_memb, g_memb);
    cudaGetSymbolAddress((void**)&p_cqb,  g_cqb);
    cudaGetSymbolAddress((void**)&p_ckb,  g_ckb);
    cudaGetSymbolAddress((void**)&p_cvb,  g_cvb);
    cudaGetSymbolAddress((void**)&p_cob,  g_cob);
    cudaGetSymbolAddress((void**)&p_hb,   g_hb);
    cudaGetSymbolAddress((void**)&p_h2b,  g_h2b);
    cudaGetSymbolAddress((void**)&p_wts,  g_wts);

    // ---- fused weight transpose (1 launch) ----
    WSrc ws;
    ws.p[0] = wq;  ws.p[1] = wk;  ws.p[2] = wv;  ws.p[3] = w_merge;
    ws.p[4] = cwq; ws.p[5] = cwk; ws.p[6] = cwv; ws.p[7] = cwo;
    ws.p[8] = mw1; ws.p[9] = mw2;
    wtrans_all<<<1024, dim3(32, 8)>>>(ws, p_wts);

    dim3 gq64(CH / 64, NLROWS / 64);       // (4,128)  BM=64
    dim3 gdual(2 * CH / 64, NLROWS / 128); // (8,64)   BM=128
    dim3 gmemd(2 * CH / 64, NSROWS / 128); // (8,128)  BM=128
    dim3 gm1(HID / 64, NLROWS / 128);      // (16,64)  BM=128

    // ---- self attention (linear attention) ----
    ln_kernel<<<NLROWS, 256>>>(tgt, ln1_g, ln1_b, tgt_pos, p_xb1, p_xb2);
    gemm_bf16<1, false, true, 128><<<gdual, 256>>>(p_xb2, p_wts + WT_WQ, bq, bk, nullptr,
                                                   p_q, p_k, NLROWS, CH, CH);
    gemm_bf16<0, false, false, 64><<<gq64, 128>>>(p_xb1, p_wts + WT_WV, bv, nullptr, nullptr,
                                                  p_v, nullptr, NLROWS, CH, CH);
    kv_accum<<<dim3(NB * NH, 8), 1024>>>();
    kv_reduce<<<NB * NH, 1024>>>();
    lin_out<<<NLROWS, 256>>>();
    gemm_bf16<2, false, false, 64><<<gq64, 128>>>(p_laob, p_wts + WT_WM, nullptr, nullptr, tgt,
                                                  p_t1, nullptr, NLROWS, CH, CH);

    // ---- cross attention ----
    ln_kernel<<<NLROWS, 256>>>(p_t1, ln2_g, ln2_b, nullptr, p_xb1, nullptr);
    mem_add<<<NSROWS * CH / 4 / 256, 256>>>(memory, pos_emb);
    gemm_bf16<0, true, false, 64><<<gq64, 128>>>(p_xb1, p_wts + WT_CWQ, cbq, nullptr, nullptr,
                                                 p_cqb, nullptr, NLROWS, CH, CH);
    gemm_bf16<0, true, true, 128><<<gmemd, 256>>>(p_memb, p_wts + WT_CWK, cbk, cbv, nullptr,
                                                  p_ckb, p_cvb, NSROWS, CH, CH);
    vtrans<<<dim3(SK / 32, NB * NH), dim3(32, 8)>>>();
    flash_attn_mma<<<dim3(LQ / 128, NH, NB), 256>>>();
    gemm_bf16<2, false, false, 64><<<gq64, 128>>>(p_cob, p_wts + WT_CWO, cbo, nullptr, p_t1,
                                                  p_t2, nullptr, NLROWS, CH, CH);

    // ---- MLP ----
    ln_kernel<<<NLROWS, 256>>>(p_t2, ln3_g, ln3_b, nullptr, p_xb1, nullptr);
    gemm_bf16<0, true, false, 128><<<gm1, 256>>>(p_xb1, p_wts + WT_MW1, mb1, nullptr, nullptr,
                                                 p_hb, nullptr, NLROWS, CH, HID);
    conv_gelu<<<NLROWS * HID / 256, 256>>>(dwk, dwb);
    gemm_bf16<2, false, false, 64><<<gq64, 128>>>(p_h2b, p_wts + WT_MW2, mb2, nullptr, p_t2,
                                                  out, nullptr, NLROWS, HID, CH);
}